// round 1
// baseline (speedup 1.0000x reference)
#include <cuda_runtime.h>
#include <cuda_bf16.h>
#include <math.h>

// ---------------------------------------------------------------------------
// DRConv restructured:
//   out[b,o,p] = bias[o] + sum_t conv_t[b,o,p] * c[b,t,p]
// where conv_t uses the shared weight template T_t (batch independent) and
//   c[b,t,p] = sum_g probs[b,g,p] * xse[b, g*8+t]
// ---------------------------------------------------------------------------

#define B_   8
#define C_   128
#define O_   128
#define H_   56
#define W_   56
#define HW_  (H_ * W_)       // 3136
#define G_   8
#define T_   8
#define KK_  1152            // C*3*3

// Scratch (device globals; no dynamic allocation allowed)
__device__ float g_gap[B_ * C_];                       // [b][c]
__device__ float g_xse[B_ * G_ * T_];                  // [b][g*8+t]
__device__ float g_c[B_ * T_ * HW_];                   // [b][t][p]
__device__ float g_wT2[T_ * C_ * 9 * O_];              // [t][ci][tap][o]
__device__ float g_y[B_ * T_ * O_ * HW_];              // [b][t][o][p]  (~103 MB)

// ---------------------------------------------------------------------------
// Stage 1a: global average pool  -> g_gap[b*C + c]
// ---------------------------------------------------------------------------
__global__ void gap_kernel(const float* __restrict__ inputs) {
    int bc = blockIdx.x;                 // 0..1023
    const float* p = inputs + (size_t)bc * HW_;
    float s = 0.f;
    for (int i = threadIdx.x; i < HW_; i += 256) s += p[i];
    // block reduction
    __shared__ float red[8];
    // warp reduce
    for (int off = 16; off > 0; off >>= 1)
        s += __shfl_down_sync(0xffffffffu, s, off);
    int lane = threadIdx.x & 31, wid = threadIdx.x >> 5;
    if (lane == 0) red[wid] = s;
    __syncthreads();
    if (wid == 0) {
        s = (lane < 8) ? red[lane] : 0.f;
        for (int off = 4; off > 0; off >>= 1)
            s += __shfl_down_sync(0xffffffffu, s, off);
        if (lane == 0) g_gap[bc] = s / (float)HW_;
    }
}

// ---------------------------------------------------------------------------
// Stage 1b: routing fc + scaled sigmoid -> g_xse[b*64 + j]
//   xse = 2*sigmoid(gap @ rw^T + rb)/8 = 0.25*sigmoid(.)
// ---------------------------------------------------------------------------
__global__ void xse_kernel(const float* __restrict__ routing_w,
                           const float* __restrict__ routing_b) {
    int b = blockIdx.x;        // 0..7
    int j = threadIdx.x;       // 0..63
    float s = routing_b[j];
    const float* gp = g_gap + b * C_;
    const float* rw = routing_w + j * C_;
    #pragma unroll 8
    for (int c = 0; c < C_; c++) s += gp[c] * rw[c];
    g_xse[b * 64 + j] = 0.25f / (1.f + expf(-s));
}

// ---------------------------------------------------------------------------
// Stage 2: per-pixel coefficients c[b,t,p]
// ---------------------------------------------------------------------------
__global__ void coeff_kernel(const float* __restrict__ Alpha,
                             const int* __restrict__ mask,
                             const void* __restrict__ use_alpha_ptr) {
    int b = blockIdx.y;
    int p = blockIdx.x * 128 + threadIdx.x;
    __shared__ float sx[64];
    if (threadIdx.x < 64) sx[threadIdx.x] = g_xse[b * 64 + threadIdx.x];
    __syncthreads();
    if (p >= HW_) return;

    bool ua = true;
    if (use_alpha_ptr) ua = (*(const int*)use_alpha_ptr) != 0;

    float pr[G_];
    if (ua) {
        float a[G_], m = -1e30f;
        #pragma unroll
        for (int g = 0; g < G_; g++) {
            a[g] = Alpha[((size_t)b * G_ + g) * HW_ + p];
            m = fmaxf(m, a[g]);
        }
        float sum = 0.f;
        #pragma unroll
        for (int g = 0; g < G_; g++) { pr[g] = expf(a[g] - m); sum += pr[g]; }
        float inv = 1.f / sum;
        #pragma unroll
        for (int g = 0; g < G_; g++) pr[g] *= inv;
    } else {
        int mk = mask[(size_t)b * HW_ + p];
        #pragma unroll
        for (int g = 0; g < G_; g++) pr[g] = (g == mk) ? 1.f : 0.f;
    }
    #pragma unroll
    for (int t = 0; t < T_; t++) {
        float s = 0.f;
        #pragma unroll
        for (int g = 0; g < G_; g++) s += pr[g] * sx[g * 8 + t];
        g_c[((size_t)b * T_ + t) * HW_ + p] = s;
    }
}

// ---------------------------------------------------------------------------
// Stage 3a: repack templates: g_wT2[((t*128+ci)*9+tap)*128+o] = wt[(o*1152+ci*9+tap)*8+t]
// ---------------------------------------------------------------------------
__global__ void repack_kernel(const float* __restrict__ wt) {
    int idx = blockIdx.x * 256 + threadIdx.x;    // < 1179648
    int o   = idx & 127;
    int rem = idx >> 7;
    int tap = rem % 9; rem /= 9;
    int ci  = rem & 127;
    int t   = rem >> 7;
    g_wT2[idx] = wt[((size_t)o * KK_ + ci * 9 + tap) * 8 + t];
}

// ---------------------------------------------------------------------------
// Stage 3b: the 8-template direct convolution.
// Block: (pixel-tile = 2 rows x 56 cols, template t, batch b)
//   computes conv_t[b, 0..127, tile] -> g_y
// 256 threads: mg = tid>>4 (16 groups of 8 output chans), pg = tid&15
//   (16 groups of 7 pixels; pg<8 -> row0, pg>=8 -> row0+1)
// ---------------------------------------------------------------------------
__global__ __launch_bounds__(256) void conv_kernel(const float* __restrict__ inputs) {
    const int t    = blockIdx.y;
    const int b    = blockIdx.z;
    const int row0 = blockIdx.x * 2;

    __shared__ float s_in[8][4][64];     // [ci][row-1..+2][col+1 (0..57)]
    __shared__ float s_w[8 * 9 * 128];   // [ci][tap][o]

    const int tid = threadIdx.x;
    const int pg  = tid & 15;
    const int mg  = tid >> 4;
    const int r   = pg >> 3;                 // output row within tile (0/1)
    const int colbase = (pg & 7) * 7;        // first of 7 output columns

    float acc[8][7];
    #pragma unroll
    for (int i = 0; i < 8; i++)
        #pragma unroll
        for (int j = 0; j < 7; j++) acc[i][j] = 0.f;

    const float* wbase = g_wT2 + (size_t)t * C_ * 9 * O_;

    for (int ci0 = 0; ci0 < C_; ci0 += 8) {
        __syncthreads();
        // ---- stage input slab: 8 ci x 4 rows x 58 cols (zero-padded) ----
        for (int idx = tid; idx < 8 * 4 * 64; idx += 256) {
            int ci = idx >> 8;
            int rr = (idx >> 6) & 3;
            int cc = idx & 63;
            int gr = row0 - 1 + rr;
            int gc = cc - 1;
            float v = 0.f;
            if ((unsigned)gr < (unsigned)H_ && (unsigned)gc < (unsigned)W_)
                v = inputs[(((size_t)b * C_ + ci0 + ci) * H_ + gr) * W_ + gc];
            s_in[ci][rr][cc] = v;
        }
        // ---- stage weights: contiguous copy (layout already [ci][tap][o]) ----
        const float* wsrc = wbase + (size_t)ci0 * 9 * O_;
        for (int idx = tid; idx < 8 * 9 * O_; idx += 256)
            s_w[idx] = wsrc[idx];
        __syncthreads();

        // ---- compute ----
        #pragma unroll
        for (int ci = 0; ci < 8; ci++) {
            #pragma unroll
            for (int kh = 0; kh < 3; kh++) {
                float inv[9];
                #pragma unroll
                for (int j = 0; j < 9; j++)
                    inv[j] = s_in[ci][r + kh][colbase + j];
                #pragma unroll
                for (int kw = 0; kw < 3; kw++) {
                    const float* wp = &s_w[(ci * 9 + kh * 3 + kw) * O_ + mg * 8];
                    float4 w0 = *(const float4*)wp;
                    float4 w1 = *(const float4*)(wp + 4);
                    float wreg[8] = {w0.x, w0.y, w0.z, w0.w, w1.x, w1.y, w1.z, w1.w};
                    #pragma unroll
                    for (int i = 0; i < 8; i++)
                        #pragma unroll
                        for (int j = 0; j < 7; j++)
                            acc[i][j] = fmaf(wreg[i], inv[j + kw], acc[i][j]);
                }
            }
        }
    }

    // ---- write partials ----
    const int orow = row0 + r;
    const size_t pbase = (size_t)orow * W_ + colbase;
    float* yb = g_y + (((size_t)b * T_ + t) * O_) * HW_;
    #pragma unroll
    for (int i = 0; i < 8; i++) {
        int o = mg * 8 + i;
        float* yp = yb + (size_t)o * HW_ + pbase;
        #pragma unroll
        for (int j = 0; j < 7; j++) yp[j] = acc[i][j];
    }
}

// ---------------------------------------------------------------------------
// Stage 4: combine: out[b,o,p] = bias[o] + sum_t g_y[b,t,o,p] * g_c[b,t,p]
// ---------------------------------------------------------------------------
__global__ void combine_kernel(const float* __restrict__ bias,
                               float* __restrict__ out) {
    size_t idx = (size_t)blockIdx.x * 256 + threadIdx.x;   // < 3,211,264
    int p   = (int)(idx % HW_);
    int rem = (int)(idx / HW_);
    int o   = rem & 127;
    int b   = rem >> 7;
    float s = bias[o];
    #pragma unroll
    for (int t = 0; t < T_; t++) {
        float y = g_y[(((size_t)b * T_ + t) * O_ + o) * HW_ + p];
        float c = g_c[((size_t)b * T_ + t) * HW_ + p];
        s = fmaf(y, c, s);
    }
    out[idx] = s;
}

// ---------------------------------------------------------------------------
extern "C" void kernel_launch(void* const* d_in, const int* in_sizes, int n_in,
                              void* d_out, int out_size) {
    const float* inputs     = (const float*)d_in[0];
    const int*   mask       = (const int*)  d_in[1];
    const float* Alpha      = (const float*)d_in[2];
    const float* wt         = (const float*)d_in[3];
    const float* routing_w  = (const float*)d_in[4];
    const float* routing_b  = (const float*)d_in[5];
    const float* bias       = (const float*)d_in[6];
    const void*  use_alpha  = (n_in > 7) ? d_in[7] : nullptr;
    float* out = (float*)d_out;

    // template repack (independent)
    repack_kernel<<<(T_ * C_ * 9 * O_) / 256, 256>>>(wt);
    // routing
    gap_kernel<<<B_ * C_, 256>>>(inputs);
    xse_kernel<<<B_, 64>>>(routing_w, routing_b);
    // per-pixel coefficients
    coeff_kernel<<<dim3((HW_ + 127) / 128, B_), 128>>>(Alpha, mask, use_alpha);
    // 8-template conv
    conv_kernel<<<dim3(H_ / 2, T_, B_), 256>>>(inputs);
    // blend + bias
    combine_kernel<<<(B_ * O_ * HW_) / 256, 256>>>(bias, out);
}

// round 2
// speedup vs baseline: 1.3663x; 1.3663x over previous
#include <cuda_runtime.h>
#include <cuda_bf16.h>
#include <math.h>

// ---------------------------------------------------------------------------
// DRConv restructured:
//   out[b,o,p] = bias[o] + sum_t conv_t[b,o,p] * c[b,t,p]
//   c[b,t,p]   = sum_g probs[b,g,p] * xse[b, g*8+t]
// conv uses packed fp32x2 FMA (FFMA2) over output-channel pairs.
// ---------------------------------------------------------------------------

#define B_   8
#define C_   128
#define O_   128
#define H_   56
#define W_   56
#define HW_  (H_ * W_)       // 3136
#define G_   8
#define T_   8
#define KK_  1152            // C*3*3

typedef unsigned long long u64;

__device__ float g_gap[B_ * C_];                       // [b][c]
__device__ float g_xse[B_ * G_ * T_];                  // [b][g*8+t]
__device__ float g_c[B_ * T_ * HW_];                   // [b][t][p]
__device__ float g_wT2[T_ * C_ * 9 * O_];              // [t][ci][tap][o]
__device__ float g_y[B_ * T_ * O_ * HW_];              // [b][t][o][p]  (~103 MB)

// ---- packed fp32x2 helpers -------------------------------------------------
__device__ __forceinline__ void ffma2(u64& d, u64 a, u64 b) {
    asm("fma.rn.f32x2 %0, %1, %2, %0;" : "+l"(d) : "l"(a), "l"(b));
}
__device__ __forceinline__ u64 bcast2(float v) {
    u64 r;
    asm("mov.b64 %0, {%1, %1};" : "=l"(r) : "f"(v));
    return r;
}
__device__ __forceinline__ void unpack2(float& lo, float& hi, u64 v) {
    asm("mov.b64 {%0, %1}, %2;" : "=f"(lo), "=f"(hi) : "l"(v));
}

// ---------------------------------------------------------------------------
// Stage 1a: global average pool
// ---------------------------------------------------------------------------
__global__ void gap_kernel(const float* __restrict__ inputs) {
    int bc = blockIdx.x;
    const float* p = inputs + (size_t)bc * HW_;
    float s = 0.f;
    for (int i = threadIdx.x; i < HW_; i += 256) s += p[i];
    __shared__ float red[8];
    for (int off = 16; off > 0; off >>= 1)
        s += __shfl_down_sync(0xffffffffu, s, off);
    int lane = threadIdx.x & 31, wid = threadIdx.x >> 5;
    if (lane == 0) red[wid] = s;
    __syncthreads();
    if (wid == 0) {
        s = (lane < 8) ? red[lane] : 0.f;
        for (int off = 4; off > 0; off >>= 1)
            s += __shfl_down_sync(0xffffffffu, s, off);
        if (lane == 0) g_gap[bc] = s / (float)HW_;
    }
}

// ---------------------------------------------------------------------------
// Stage 1b: routing fc + scaled sigmoid
// ---------------------------------------------------------------------------
__global__ void xse_kernel(const float* __restrict__ routing_w,
                           const float* __restrict__ routing_b) {
    int b = blockIdx.x;
    int j = threadIdx.x;
    float s = routing_b[j];
    const float* gp = g_gap + b * C_;
    const float* rw = routing_w + j * C_;
    #pragma unroll 8
    for (int c = 0; c < C_; c++) s += gp[c] * rw[c];
    g_xse[b * 64 + j] = 0.25f / (1.f + expf(-s));
}

// ---------------------------------------------------------------------------
// Stage 2: per-pixel coefficients c[b,t,p]
// ---------------------------------------------------------------------------
__global__ void coeff_kernel(const float* __restrict__ Alpha,
                             const int* __restrict__ mask,
                             const void* __restrict__ use_alpha_ptr) {
    int b = blockIdx.y;
    int p = blockIdx.x * 128 + threadIdx.x;
    __shared__ float sx[64];
    if (threadIdx.x < 64) sx[threadIdx.x] = g_xse[b * 64 + threadIdx.x];
    __syncthreads();
    if (p >= HW_) return;

    bool ua = true;
    if (use_alpha_ptr) ua = (*(const int*)use_alpha_ptr) != 0;

    float pr[G_];
    if (ua) {
        float a[G_], m = -1e30f;
        #pragma unroll
        for (int g = 0; g < G_; g++) {
            a[g] = Alpha[((size_t)b * G_ + g) * HW_ + p];
            m = fmaxf(m, a[g]);
        }
        float sum = 0.f;
        #pragma unroll
        for (int g = 0; g < G_; g++) { pr[g] = expf(a[g] - m); sum += pr[g]; }
        float inv = 1.f / sum;
        #pragma unroll
        for (int g = 0; g < G_; g++) pr[g] *= inv;
    } else {
        int mk = mask[(size_t)b * HW_ + p];
        #pragma unroll
        for (int g = 0; g < G_; g++) pr[g] = (g == mk) ? 1.f : 0.f;
    }
    #pragma unroll
    for (int t = 0; t < T_; t++) {
        float s = 0.f;
        #pragma unroll
        for (int g = 0; g < G_; g++) s += pr[g] * sx[g * 8 + t];
        g_c[((size_t)b * T_ + t) * HW_ + p] = s;
    }
}

// ---------------------------------------------------------------------------
// Stage 3a: template repack -> [t][ci][tap][o]
// ---------------------------------------------------------------------------
__global__ void repack_kernel(const float* __restrict__ wt) {
    int idx = blockIdx.x * 256 + threadIdx.x;
    int o   = idx & 127;
    int rem = idx >> 7;
    int tap = rem % 9; rem /= 9;
    int ci  = rem & 127;
    int t   = rem >> 7;
    g_wT2[idx] = wt[((size_t)o * KK_ + ci * 9 + tap) * 8 + t];
}

// ---------------------------------------------------------------------------
// Stage 3b: 8-template conv with packed f32x2 FMA.
// Block tile: 4 output rows x 56 cols x 128 oc, for one (b, t).
// 256 threads: mg = tid>>4 (16 x 8-oc groups), pg = (tid>>2)&3 (4 x 14-col
// groups), r = tid&3 (4 rows). Each thread: 8 oc (4 pairs) x 14 px.
// ---------------------------------------------------------------------------
#define BK_ 4
__global__ __launch_bounds__(256, 1) void conv_kernel(const float* __restrict__ inputs) {
    const int t    = blockIdx.y;
    const int b    = blockIdx.z;
    const int row0 = blockIdx.x * 4;

    __shared__ float s_in[BK_][6][64];       // [ci][row-1..+4][col pad 0..57]
    __shared__ float s_w[BK_ * 9 * O_];      // [ci][tap][o]

    const int tid = threadIdx.x;
    const int mg  = tid >> 4;                // 0..15 : oc base = mg*8
    const int pg  = (tid >> 2) & 3;          // 0..3  : col base = pg*14
    const int r   = tid & 3;                 // 0..3  : row within tile
    const int colbase = pg * 14;

    u64 acc[4][14];
    #pragma unroll
    for (int i = 0; i < 4; i++)
        #pragma unroll
        for (int j = 0; j < 14; j++) acc[i][j] = 0ULL;

    const float* wbase = g_wT2 + (size_t)t * C_ * 9 * O_;

    for (int ci0 = 0; ci0 < C_; ci0 += BK_) {
        __syncthreads();
        // ---- stage input slab: BK ci x 6 rows x 58(64) cols, zero padded ----
        #pragma unroll
        for (int k = 0; k < (BK_ * 6 * 64) / 256; k++) {
            int idx = k * 256 + tid;
            int ci = idx / 384;
            int rr = (idx >> 6) % 6;
            int cc = idx & 63;
            int gr = row0 - 1 + rr;
            int gc = cc - 1;
            float v = 0.f;
            if ((unsigned)gr < (unsigned)H_ && (unsigned)gc < (unsigned)W_)
                v = inputs[(((size_t)b * C_ + ci0 + ci) * H_ + gr) * W_ + gc];
            s_in[ci][rr][cc] = v;
        }
        // ---- stage weights (already [ci][tap][o] contiguous) ----
        {
            const float4* wsrc = (const float4*)(wbase + (size_t)ci0 * 9 * O_);
            float4* wdst = (float4*)s_w;
            #pragma unroll
            for (int k = 0; k < (BK_ * 9 * O_ / 4 + 255) / 256; k++) {
                int idx = k * 256 + tid;
                if (idx < BK_ * 9 * O_ / 4) wdst[idx] = wsrc[idx];
            }
        }
        __syncthreads();

        // ---- compute ----
        #pragma unroll
        for (int ci = 0; ci < BK_; ci++) {
            #pragma unroll
            for (int kh = 0; kh < 3; kh++) {
                u64 bi[16];
                #pragma unroll
                for (int m = 0; m < 16; m++)
                    bi[m] = bcast2(s_in[ci][r + kh][colbase + m]);
                #pragma unroll
                for (int kw = 0; kw < 3; kw++) {
                    const ulonglong2* wp = (const ulonglong2*)
                        &s_w[(ci * 9 + kh * 3 + kw) * O_ + mg * 8];
                    ulonglong2 wa = wp[0];
                    ulonglong2 wb = wp[1];
                    #pragma unroll
                    for (int j = 0; j < 14; j++) {
                        ffma2(acc[0][j], wa.x, bi[j + kw]);
                        ffma2(acc[1][j], wa.y, bi[j + kw]);
                        ffma2(acc[2][j], wb.x, bi[j + kw]);
                        ffma2(acc[3][j], wb.y, bi[j + kw]);
                    }
                }
            }
        }
    }

    // ---- write partials ----
    const int orow = row0 + r;
    const size_t pbase = (size_t)orow * W_ + colbase;
    float* yb = g_y + (((size_t)b * T_ + t) * O_) * HW_;
    #pragma unroll
    for (int i = 0; i < 4; i++) {
        int oc0 = mg * 8 + 2 * i;
        float* yp0 = yb + (size_t)oc0 * HW_ + pbase;
        float* yp1 = yp0 + HW_;
        #pragma unroll
        for (int j = 0; j < 14; j++) {
            float lo, hi;
            unpack2(lo, hi, acc[i][j]);
            yp0[j] = lo;
            yp1[j] = hi;
        }
    }
}

// ---------------------------------------------------------------------------
// Stage 4: combine: out[b,o,p] = bias[o] + sum_t g_y[b,t,o,p] * g_c[b,t,p]
// ---------------------------------------------------------------------------
__global__ void combine_kernel(const float* __restrict__ bias,
                               float* __restrict__ out) {
    size_t idx = (size_t)blockIdx.x * 256 + threadIdx.x;
    int p   = (int)(idx % HW_);
    int rem = (int)(idx / HW_);
    int o   = rem & 127;
    int b   = rem >> 7;
    float s = bias[o];
    #pragma unroll
    for (int t = 0; t < T_; t++) {
        float y = g_y[(((size_t)b * T_ + t) * O_ + o) * HW_ + p];
        float c = g_c[((size_t)b * T_ + t) * HW_ + p];
        s = fmaf(y, c, s);
    }
    out[idx] = s;
}

// ---------------------------------------------------------------------------
extern "C" void kernel_launch(void* const* d_in, const int* in_sizes, int n_in,
                              void* d_out, int out_size) {
    const float* inputs     = (const float*)d_in[0];
    const int*   mask       = (const int*)  d_in[1];
    const float* Alpha      = (const float*)d_in[2];
    const float* wt         = (const float*)d_in[3];
    const float* routing_w  = (const float*)d_in[4];
    const float* routing_b  = (const float*)d_in[5];
    const float* bias       = (const float*)d_in[6];
    const void*  use_alpha  = (n_in > 7) ? d_in[7] : nullptr;
    float* out = (float*)d_out;

    repack_kernel<<<(T_ * C_ * 9 * O_) / 256, 256>>>(wt);
    gap_kernel<<<B_ * C_, 256>>>(inputs);
    xse_kernel<<<B_, 64>>>(routing_w, routing_b);
    coeff_kernel<<<dim3((HW_ + 127) / 128, B_), 128>>>(Alpha, mask, use_alpha);
    conv_kernel<<<dim3(H_ / 4, T_, B_), 256>>>(inputs);
    combine_kernel<<<(B_ * O_ * HW_) / 256, 256>>>(bias, out);
}

// round 6
// speedup vs baseline: 1.3667x; 1.0003x over previous
#include <cuda_runtime.h>
#include <cuda_bf16.h>
#include <math.h>

// ---------------------------------------------------------------------------
// DRConv restructured:
//   out[b,o,p] = bias[o] + sum_t conv_t[b,o,p] * c[b,t,p]
//   c[b,t,p]   = sum_g probs[b,g,p] * xse[b, g*8+t]
// conv uses packed fp32x2 FMA (FFMA2) over output-channel pairs.
// ---------------------------------------------------------------------------

#define B_   8
#define C_   128
#define O_   128
#define H_   56
#define W_   56
#define HW_  (H_ * W_)       // 3136
#define G_   8
#define T_   8
#define KK_  1152            // C*3*3

typedef unsigned long long u64;

__device__ float g_gap[B_ * C_];                       // [b][c]
__device__ float g_xse[B_ * G_ * T_];                  // [b][g*8+t]
__device__ float g_c[B_ * T_ * HW_];                   // [b][t][p]
__device__ float g_wT2[T_ * C_ * 9 * O_];              // [t][ci][tap][o]
__device__ float g_y[B_ * T_ * O_ * HW_];              // [b][t][o][p]  (~103 MB)

// ---- packed fp32x2 helpers -------------------------------------------------
__device__ __forceinline__ void ffma2(u64& d, u64 a, u64 b) {
    asm("fma.rn.f32x2 %0, %1, %2, %0;" : "+l"(d) : "l"(a), "l"(b));
}
__device__ __forceinline__ u64 bcast2(float v) {
    u64 r;
    asm("mov.b64 %0, {%1, %1};" : "=l"(r) : "f"(v));
    return r;
}
__device__ __forceinline__ void unpack2(float& lo, float& hi, u64 v) {
    asm("mov.b64 {%0, %1}, %2;" : "=f"(lo), "=f"(hi) : "l"(v));
}

// ---------------------------------------------------------------------------
// Stage 1a: global average pool
// ---------------------------------------------------------------------------
__global__ void gap_kernel(const float* __restrict__ inputs) {
    int bc = blockIdx.x;
    const float* p = inputs + (size_t)bc * HW_;
    float s = 0.f;
    for (int i = threadIdx.x; i < HW_; i += 256) s += p[i];
    __shared__ float red[8];
    for (int off = 16; off > 0; off >>= 1)
        s += __shfl_down_sync(0xffffffffu, s, off);
    int lane = threadIdx.x & 31, wid = threadIdx.x >> 5;
    if (lane == 0) red[wid] = s;
    __syncthreads();
    if (wid == 0) {
        s = (lane < 8) ? red[lane] : 0.f;
        for (int off = 4; off > 0; off >>= 1)
            s += __shfl_down_sync(0xffffffffu, s, off);
        if (lane == 0) g_gap[bc] = s / (float)HW_;
    }
}

// ---------------------------------------------------------------------------
// Stage 1b: routing fc + scaled sigmoid
// ---------------------------------------------------------------------------
__global__ void xse_kernel(const float* __restrict__ routing_w,
                           const float* __restrict__ routing_b) {
    int b = blockIdx.x;
    int j = threadIdx.x;
    float s = routing_b[j];
    const float* gp = g_gap + b * C_;
    const float* rw = routing_w + j * C_;
    #pragma unroll 8
    for (int c = 0; c < C_; c++) s += gp[c] * rw[c];
    g_xse[b * 64 + j] = 0.25f / (1.f + expf(-s));
}

// ---------------------------------------------------------------------------
// Stage 2: per-pixel coefficients c[b,t,p]
// ---------------------------------------------------------------------------
__global__ void coeff_kernel(const float* __restrict__ Alpha,
                             const int* __restrict__ mask,
                             const void* __restrict__ use_alpha_ptr) {
    int b = blockIdx.y;
    int p = blockIdx.x * 128 + threadIdx.x;
    __shared__ float sx[64];
    if (threadIdx.x < 64) sx[threadIdx.x] = g_xse[b * 64 + threadIdx.x];
    __syncthreads();
    if (p >= HW_) return;

    bool ua = true;
    if (use_alpha_ptr) ua = (*(const int*)use_alpha_ptr) != 0;

    float pr[G_];
    if (ua) {
        float a[G_], m = -1e30f;
        #pragma unroll
        for (int g = 0; g < G_; g++) {
            a[g] = Alpha[((size_t)b * G_ + g) * HW_ + p];
            m = fmaxf(m, a[g]);
        }
        float sum = 0.f;
        #pragma unroll
        for (int g = 0; g < G_; g++) { pr[g] = expf(a[g] - m); sum += pr[g]; }
        float inv = 1.f / sum;
        #pragma unroll
        for (int g = 0; g < G_; g++) pr[g] *= inv;
    } else {
        int mk = mask[(size_t)b * HW_ + p];
        #pragma unroll
        for (int g = 0; g < G_; g++) pr[g] = (g == mk) ? 1.f : 0.f;
    }
    #pragma unroll
    for (int t = 0; t < T_; t++) {
        float s = 0.f;
        #pragma unroll
        for (int g = 0; g < G_; g++) s += pr[g] * sx[g * 8 + t];
        g_c[((size_t)b * T_ + t) * HW_ + p] = s;
    }
}

// ---------------------------------------------------------------------------
// Stage 3a: template repack -> [t][ci][tap][o]
// ---------------------------------------------------------------------------
__global__ void repack_kernel(const float* __restrict__ wt) {
    int idx = blockIdx.x * 256 + threadIdx.x;
    int o   = idx & 127;
    int rem = idx >> 7;
    int tap = rem % 9; rem /= 9;
    int ci  = rem & 127;
    int t   = rem >> 7;
    g_wT2[idx] = wt[((size_t)o * KK_ + ci * 9 + tap) * 8 + t];
}

// ---------------------------------------------------------------------------
// Stage 3b: 8-template conv with packed f32x2 FMA.
// Block tile: 4 output rows x 56 cols x 128 oc, for one (b, t).
// 256 threads: mg = tid>>4 (16 x 8-oc groups), pg = (tid>>2)&3 (4 x 14-col
// groups), r = tid&3 (4 rows). Each thread: 8 oc (4 pairs) x 14 px.
// ---------------------------------------------------------------------------
#define BK_ 4
__global__ __launch_bounds__(256, 1) void conv_kernel(const float* __restrict__ inputs) {
    const int t    = blockIdx.y;
    const int b    = blockIdx.z;
    const int row0 = blockIdx.x * 4;

    __shared__ float s_in[BK_][6][64];       // [ci][row-1..+4][col pad 0..57]
    __shared__ float s_w[BK_ * 9 * O_];      // [ci][tap][o]

    const int tid = threadIdx.x;
    const int mg  = tid >> 4;                // 0..15 : oc base = mg*8
    const int pg  = (tid >> 2) & 3;          // 0..3  : col base = pg*14
    const int r   = tid & 3;                 // 0..3  : row within tile
    const int colbase = pg * 14;

    u64 acc[4][14];
    #pragma unroll
    for (int i = 0; i < 4; i++)
        #pragma unroll
        for (int j = 0; j < 14; j++) acc[i][j] = 0ULL;

    const float* wbase = g_wT2 + (size_t)t * C_ * 9 * O_;

    for (int ci0 = 0; ci0 < C_; ci0 += BK_) {
        __syncthreads();
        // ---- stage input slab: BK ci x 6 rows x 58(64) cols, zero padded ----
        #pragma unroll
        for (int k = 0; k < (BK_ * 6 * 64) / 256; k++) {
            int idx = k * 256 + tid;
            int ci = idx / 384;
            int rr = (idx >> 6) % 6;
            int cc = idx & 63;
            int gr = row0 - 1 + rr;
            int gc = cc - 1;
            float v = 0.f;
            if ((unsigned)gr < (unsigned)H_ && (unsigned)gc < (unsigned)W_)
                v = inputs[(((size_t)b * C_ + ci0 + ci) * H_ + gr) * W_ + gc];
            s_in[ci][rr][cc] = v;
        }
        // ---- stage weights (already [ci][tap][o] contiguous) ----
        {
            const float4* wsrc = (const float4*)(wbase + (size_t)ci0 * 9 * O_);
            float4* wdst = (float4*)s_w;
            #pragma unroll
            for (int k = 0; k < (BK_ * 9 * O_ / 4 + 255) / 256; k++) {
                int idx = k * 256 + tid;
                if (idx < BK_ * 9 * O_ / 4) wdst[idx] = wsrc[idx];
            }
        }
        __syncthreads();

        // ---- compute ----
        #pragma unroll
        for (int ci = 0; ci < BK_; ci++) {
            #pragma unroll
            for (int kh = 0; kh < 3; kh++) {
                u64 bi[16];
                #pragma unroll
                for (int m = 0; m < 16; m++)
                    bi[m] = bcast2(s_in[ci][r + kh][colbase + m]);
                #pragma unroll
                for (int kw = 0; kw < 3; kw++) {
                    const ulonglong2* wp = (const ulonglong2*)
                        &s_w[(ci * 9 + kh * 3 + kw) * O_ + mg * 8];
                    ulonglong2 wa = wp[0];
                    ulonglong2 wb = wp[1];
                    #pragma unroll
                    for (int j = 0; j < 14; j++) {
                        ffma2(acc[0][j], wa.x, bi[j + kw]);
                        ffma2(acc[1][j], wa.y, bi[j + kw]);
                        ffma2(acc[2][j], wb.x, bi[j + kw]);
                        ffma2(acc[3][j], wb.y, bi[j + kw]);
                    }
                }
            }
        }
    }

    // ---- write partials ----
    const int orow = row0 + r;
    const size_t pbase = (size_t)orow * W_ + colbase;
    float* yb = g_y + (((size_t)b * T_ + t) * O_) * HW_;
    #pragma unroll
    for (int i = 0; i < 4; i++) {
        int oc0 = mg * 8 + 2 * i;
        float* yp0 = yb + (size_t)oc0 * HW_ + pbase;
        float* yp1 = yp0 + HW_;
        #pragma unroll
        for (int j = 0; j < 14; j++) {
            float lo, hi;
            unpack2(lo, hi, acc[i][j]);
            yp0[j] = lo;
            yp1[j] = hi;
        }
    }
}

// ---------------------------------------------------------------------------
// Stage 4: combine: out[b,o,p] = bias[o] + sum_t g_y[b,t,o,p] * g_c[b,t,p]
// ---------------------------------------------------------------------------
__global__ void combine_kernel(const float* __restrict__ bias,
                               float* __restrict__ out) {
    size_t idx = (size_t)blockIdx.x * 256 + threadIdx.x;
    int p   = (int)(idx % HW_);
    int rem = (int)(idx / HW_);
    int o   = rem & 127;
    int b   = rem >> 7;
    float s = bias[o];
    #pragma unroll
    for (int t = 0; t < T_; t++) {
        float y = g_y[(((size_t)b * T_ + t) * O_ + o) * HW_ + p];
        float c = g_c[((size_t)b * T_ + t) * HW_ + p];
        s = fmaf(y, c, s);
    }
    out[idx] = s;
}

// ---------------------------------------------------------------------------
extern "C" void kernel_launch(void* const* d_in, const int* in_sizes, int n_in,
                              void* d_out, int out_size) {
    const float* inputs     = (const float*)d_in[0];
    const int*   mask       = (const int*)  d_in[1];
    const float* Alpha      = (const float*)d_in[2];
    const float* wt         = (const float*)d_in[3];
    const float* routing_w  = (const float*)d_in[4];
    const float* routing_b  = (const float*)d_in[5];
    const float* bias       = (const float*)d_in[6];
    const void*  use_alpha  = (n_in > 7) ? d_in[7] : nullptr;
    float* out = (float*)d_out;

    repack_kernel<<<(T_ * C_ * 9 * O_) / 256, 256>>>(wt);
    gap_kernel<<<B_ * C_, 256>>>(inputs);
    xse_kernel<<<B_, 64>>>(routing_w, routing_b);
    coeff_kernel<<<dim3((HW_ + 127) / 128, B_), 128>>>(Alpha, mask, use_alpha);
    conv_kernel<<<dim3(H_ / 4, T_, B_), 256>>>(inputs);
    combine_kernel<<<(B_ * O_ * HW_) / 256, 256>>>(bias, out);
}

// round 8
// speedup vs baseline: 3.5249x; 2.5791x over previous
#include <cuda_runtime.h>
#include <cuda_fp16.h>
#include <math.h>
#include <stdint.h>

// ===========================================================================
// DRConv via warp-level fp16 tensor cores (mma.sync.m16n8k16, plain sm_103):
//   out[b,o,p] = bias[o] + sum_t c[b,t,p] * (W_t (*) x)[b,o,p]
//   c[b,t,p]   = sum_g probs[b,g,p] * xse[b, g*8+t]
// Conv = per-tap GEMMs on zero-padded NHWC input (flat-shift im2col).
// Precision: x = x_hi + x_lo (fp16 pair, exact to 2^-22); w rounded to fp16
// (rel 2^-12). Two MMA terms: w*x_hi + w*x_lo, fp32 accumulate.
// ===========================================================================

#define B_    8
#define C_    128
#define O_    128
#define H_    56
#define W_    56
#define HW_   3136
#define G_    8
#define T_    8
#define PW_   58
#define PQ_   (PW_*PW_)        // 3364
#define QPAD_ 3456             // 27*128
#define PROW_ 3712             // 64 guard + 3364 + guard

// ---------------- device scratch (static; zero-initialized) ----------------
__device__ __align__(128) __half g_Ph[B_*PROW_*C_];     // 7.6 MB input hi
__device__ __align__(128) __half g_Pl[B_*PROW_*C_];     // 7.6 MB input lo
__device__ __align__(128) __half g_Wh[T_*9*O_*C_];      // 2.36 MB weights
__device__ float g_gap[B_*C_];
__device__ float g_xse[B_*64];
__device__ float g_cq[B_*T_*QPAD_];
__device__ float g_part[T_*B_*O_*QPAD_];                // 113 MB [t][b][oc][q]

// ---------------- PTX helpers ----------------
__device__ __forceinline__ uint32_t smem_u32(const void* p) {
    uint32_t a;
    asm("{ .reg .u64 t; cvta.to.shared.u64 t, %1; cvt.u32.u64 %0, t; }" : "=r"(a) : "l"(p));
    return a;
}
__device__ __forceinline__ void ldm4(uint32_t r[4], uint32_t addr) {
    asm volatile("ldmatrix.sync.aligned.m8n8.x4.shared.b16 {%0,%1,%2,%3}, [%4];"
        : "=r"(r[0]), "=r"(r[1]), "=r"(r[2]), "=r"(r[3]) : "r"(addr));
}
__device__ __forceinline__ void mma16816(float d[4], const uint32_t a[4],
                                         uint32_t b0, uint32_t b1) {
    asm volatile("mma.sync.aligned.m16n8k16.row.col.f32.f16.f16.f32 "
        "{%0,%1,%2,%3}, {%4,%5,%6,%7}, {%8,%9}, {%0,%1,%2,%3};"
        : "+f"(d[0]), "+f"(d[1]), "+f"(d[2]), "+f"(d[3])
        : "r"(a[0]), "r"(a[1]), "r"(a[2]), "r"(a[3]), "r"(b0), "r"(b1));
}
__device__ __forceinline__ void cpasync16(uint32_t saddr, const void* g) {
    asm volatile("cp.async.cg.shared.global [%0], [%1], 16;" :: "r"(saddr), "l"(g));
}

// ---------------------------------------------------------------------------
// Prep: padded NHWC hi/lo fp16 split of input (transpose via smem)
// ---------------------------------------------------------------------------
__global__ void prep_p_kernel(const float* __restrict__ inputs) {
    __shared__ float tile[128 * 57];
    int h = blockIdx.x, b = blockIdx.y, tid = threadIdx.x;
    for (int idx = tid; idx < 128 * 56; idx += 256) {
        int ci = idx / 56, w = idx % 56;
        tile[ci * 57 + w] = inputs[(((size_t)b * C_ + ci) * H_ + h) * W_ + w];
    }
    __syncthreads();
    for (int idx = tid; idx < 56 * 128; idx += 256) {
        int w = idx >> 7, ci = idx & 127;
        float x = tile[ci * 57 + w];
        __half hi = __float2half(x);
        __half lo = __float2half(x - __half2float(hi));
        size_t row = (size_t)b * PROW_ + 64 + (h + 1) * PW_ + (w + 1);
        g_Ph[row * C_ + ci] = hi;
        g_Pl[row * C_ + ci] = lo;
    }
}

// Prep: template repack -> [(t*9+tap)][o][ci] fp16
__global__ void prep_w_kernel(const float* __restrict__ wt) {
    int idx = blockIdx.x * 256 + threadIdx.x;
    if (idx >= T_ * 9 * O_ * C_) return;
    int ci = idx & 127;
    int o  = (idx >> 7) & 127;
    int tt = idx >> 14;
    int t = tt / 9, tap = tt % 9;
    g_Wh[idx] = __float2half(wt[((size_t)o * 1152 + ci * 9 + tap) * 8 + t]);
}

// ---------------------------------------------------------------------------
// Routing
// ---------------------------------------------------------------------------
__global__ void gap_kernel(const float* __restrict__ inputs) {
    int bc = blockIdx.x;
    const float* p = inputs + (size_t)bc * HW_;
    float s = 0.f;
    for (int i = threadIdx.x; i < HW_; i += 256) s += p[i];
    __shared__ float red[8];
    for (int off = 16; off > 0; off >>= 1) s += __shfl_down_sync(0xffffffffu, s, off);
    int lane = threadIdx.x & 31, wid = threadIdx.x >> 5;
    if (lane == 0) red[wid] = s;
    __syncthreads();
    if (wid == 0) {
        s = (lane < 8) ? red[lane] : 0.f;
        for (int off = 4; off > 0; off >>= 1) s += __shfl_down_sync(0xffffffffu, s, off);
        if (lane == 0) g_gap[bc] = s / (float)HW_;
    }
}
__global__ void xse_kernel(const float* __restrict__ routing_w,
                           const float* __restrict__ routing_b) {
    int b = blockIdx.x, j = threadIdx.x;
    float s = routing_b[j];
    const float* gp = g_gap + b * C_;
    const float* rw = routing_w + j * C_;
    #pragma unroll 8
    for (int c = 0; c < C_; c++) s += gp[c] * rw[c];
    g_xse[b * 64 + j] = 0.25f / (1.f + expf(-s));
}

// ---------------------------------------------------------------------------
// Per-pixel coefficients on padded q grid (0 on borders)
// ---------------------------------------------------------------------------
__global__ void coeff_kernel(const float* __restrict__ Alpha,
                             const int* __restrict__ mask,
                             const void* __restrict__ use_alpha_ptr) {
    int b = blockIdx.y;
    int q = blockIdx.x * 128 + threadIdx.x;
    __shared__ float sx[64];
    if (threadIdx.x < 64) sx[threadIdx.x] = g_xse[b * 64 + threadIdx.x];
    __syncthreads();
    if (q >= QPAD_) return;
    int h = q / PW_ - 1, w = q % PW_ - 1;
    bool valid = (h >= 0 && h < H_ && w >= 0 && w < W_ && q < PQ_);
    if (!valid) {
        #pragma unroll
        for (int t = 0; t < T_; t++) g_cq[((size_t)b * T_ + t) * QPAD_ + q] = 0.f;
        return;
    }
    int p = h * W_ + w;
    bool ua = true;
    if (use_alpha_ptr) ua = (*(const int*)use_alpha_ptr) != 0;
    float pr[G_];
    if (ua) {
        float a[G_], m = -1e30f;
        #pragma unroll
        for (int g = 0; g < G_; g++) {
            a[g] = Alpha[((size_t)b * G_ + g) * HW_ + p];
            m = fmaxf(m, a[g]);
        }
        float sum = 0.f;
        #pragma unroll
        for (int g = 0; g < G_; g++) { pr[g] = expf(a[g] - m); sum += pr[g]; }
        float inv = 1.f / sum;
        #pragma unroll
        for (int g = 0; g < G_; g++) pr[g] *= inv;
    } else {
        int mk = mask[(size_t)b * HW_ + p];
        #pragma unroll
        for (int g = 0; g < G_; g++) pr[g] = (g == mk) ? 1.f : 0.f;
    }
    #pragma unroll
    for (int t = 0; t < T_; t++) {
        float s = 0.f;
        #pragma unroll
        for (int g = 0; g < G_; g++) s += pr[g] * sx[g * 8 + t];
        g_cq[((size_t)b * T_ + t) * QPAD_ + q] = s;
    }
}

// ---------------------------------------------------------------------------
// Conv via mma.sync. Grid (27, 8, 8) = (qg, t, b); 256 threads, 8 warps 4x2.
// Per stage (tap, 32-ci chunk): A = W[128oc x 32ci], Bh/Bl = X[128px x 32ci],
// smem rows padded to 80B (conflict-free ldmatrix), cp.async 3-deep pipeline.
// ---------------------------------------------------------------------------
#define STR_    80
#define ATILE_  (128 * STR_)          // 10240
#define BUFSZ2_ (3 * ATILE_)          // 30720
#define NBUF_   3
#define CS2_    (NBUF_ * BUFSZ2_)     // 92160
#define SMEM2_  (CS2_ + 512)
#define NST_    36

__global__ __launch_bounds__(256, 2) void conv_mma_kernel() {
    extern __shared__ char sb[];
    const uint32_t s0 = smem_u32(sb);
    const int tid  = threadIdx.x;
    const int lane = tid & 31, wid = tid >> 5;
    const int wm = wid >> 1, wn = wid & 1;
    const int q0 = blockIdx.x * 128;
    const int t  = blockIdx.y;
    const int b  = blockIdx.z;

    if (tid < 128)
        ((float*)(sb + CS2_))[tid] = g_cq[((size_t)b * T_ + t) * QPAD_ + q0 + tid];

    const size_t prow0 = (size_t)b * PROW_ + 64 + q0;
    const int lr = (lane & 7) + ((lane >> 3) & 1) * 8;   // row within 16
    const int kg = lane >> 4;                             // k-halves 0/1
    const int dsh[9] = { -PW_-1, -PW_, -PW_+1, -1, 0, 1, PW_-1, PW_, PW_+1 };

    float d[2][8][4];
    #pragma unroll
    for (int i = 0; i < 2; i++)
        #pragma unroll
        for (int j = 0; j < 8; j++)
            #pragma unroll
            for (int k = 0; k < 4; k++) d[i][j][k] = 0.f;

    auto issue = [&](int s) {
        int tap = s >> 2, ch = s & 3;
        uint32_t bu = s0 + (s % NBUF_) * BUFSZ2_;
        const __half* gA = g_Wh + (((size_t)t * 9 + tap) * 128) * 128 + ch * 32;
        const __half* gBh = g_Ph + (prow0 + dsh[tap]) * 128 + ch * 32;
        const __half* gBl = g_Pl + (prow0 + dsh[tap]) * 128 + ch * 32;
        #pragma unroll
        for (int it = 0; it < 2; it++) {
            int idx = it * 256 + tid;
            int row = idx >> 2, qq = idx & 3;
            uint32_t so = row * STR_ + qq * 16;
            size_t go = (size_t)row * 128 + qq * 8;
            cpasync16(bu + so,              gA  + go);
            cpasync16(bu + ATILE_ + so,     gBh + go);
            cpasync16(bu + 2 * ATILE_ + so, gBl + go);
        }
        asm volatile("cp.async.commit_group;" ::: "memory");
    };

    issue(0); issue(1);

    for (int s = 0; s < NST_; s++) {
        if (s < NST_ - 2) asm volatile("cp.async.wait_group 1;" ::: "memory");
        else              asm volatile("cp.async.wait_group 0;" ::: "memory");
        __syncthreads();

        uint32_t bu = s0 + (s % NBUF_) * BUFSZ2_;
        #pragma unroll
        for (int ks = 0; ks < 2; ks++) {
            uint32_t koff = ks * 32 + kg * 16;
            uint32_t a0[4], a1[4];
            ldm4(a0, bu + (wm * 32 + 0  + lr) * STR_ + koff);
            ldm4(a1, bu + (wm * 32 + 16 + lr) * STR_ + koff);
            #pragma unroll
            for (int hl = 0; hl < 2; hl++) {
                uint32_t bt = bu + ATILE_ * (1 + hl);
                #pragma unroll
                for (int pr = 0; pr < 4; pr++) {
                    uint32_t bb[4];
                    ldm4(bb, bt + (wn * 64 + pr * 16 + lr) * STR_ + koff);
                    mma16816(d[0][2*pr],   a0, bb[0], bb[2]);
                    mma16816(d[0][2*pr+1], a0, bb[1], bb[3]);
                    mma16816(d[1][2*pr],   a1, bb[0], bb[2]);
                    mma16816(d[1][2*pr+1], a1, bb[1], bb[3]);
                }
            }
        }
        if (s + 2 < NST_) issue(s + 2);
    }

    // epilogue: scale by c[t][px], write partials
    const float* cs = (const float*)(sb + CS2_);
    float* pbase = g_part + (((size_t)t * B_ + b) * O_) * QPAD_;
    const int r0 = lane >> 2;
    const int c0 = 2 * (lane & 3);
    #pragma unroll
    for (int mt = 0; mt < 2; mt++) {
        int oc = wm * 32 + mt * 16 + r0;
        #pragma unroll
        for (int nt = 0; nt < 8; nt++) {
            int px = wn * 64 + nt * 8 + c0;
            float cc0 = cs[px], cc1 = cs[px + 1];
            float2 v0 = make_float2(d[mt][nt][0] * cc0, d[mt][nt][1] * cc1);
            float2 v1 = make_float2(d[mt][nt][2] * cc0, d[mt][nt][3] * cc1);
            *(float2*)(pbase + (size_t)oc * QPAD_ + q0 + px) = v0;
            *(float2*)(pbase + (size_t)(oc + 8) * QPAD_ + q0 + px) = v1;
        }
    }
}

// ---------------------------------------------------------------------------
// Combine: out = bias + sum over 8 template partials
// ---------------------------------------------------------------------------
__global__ void combine_kernel(const float* __restrict__ bias,
                               float* __restrict__ out) {
    size_t idx = (size_t)blockIdx.x * 256 + threadIdx.x;
    int p   = (int)(idx % HW_);
    int rem = (int)(idx / HW_);
    int o   = rem & 127;
    int b   = rem >> 7;
    int h = p / W_, w = p % W_;
    int q = (h + 1) * PW_ + (w + 1);
    float s = bias[o];
    #pragma unroll
    for (int t = 0; t < T_; t++)
        s += g_part[(((size_t)t * B_ + b) * O_ + o) * QPAD_ + q];
    out[idx] = s;
}

// ---------------------------------------------------------------------------
extern "C" void kernel_launch(void* const* d_in, const int* in_sizes, int n_in,
                              void* d_out, int out_size) {
    const float* inputs     = (const float*)d_in[0];
    const int*   mask       = (const int*)  d_in[1];
    const float* Alpha      = (const float*)d_in[2];
    const float* wt         = (const float*)d_in[3];
    const float* routing_w  = (const float*)d_in[4];
    const float* routing_b  = (const float*)d_in[5];
    const float* bias       = (const float*)d_in[6];
    const void*  use_alpha  = (n_in > 7) ? d_in[7] : nullptr;
    float* out = (float*)d_out;

    cudaFuncSetAttribute(conv_mma_kernel,
                         cudaFuncAttributeMaxDynamicSharedMemorySize, SMEM2_);

    prep_w_kernel<<<(T_ * 9 * O_ * C_ + 255) / 256, 256>>>(wt);
    prep_p_kernel<<<dim3(H_, B_), 256>>>(inputs);
    gap_kernel<<<B_ * C_, 256>>>(inputs);
    xse_kernel<<<B_, 64>>>(routing_w, routing_b);
    coeff_kernel<<<dim3(QPAD_ / 128, B_), 128>>>(Alpha, mask, use_alpha);
    conv_mma_kernel<<<dim3(QPAD_ / 128, T_, B_), 256, SMEM2_>>>();
    combine_kernel<<<(B_ * O_ * HW_) / 256, 256>>>(bias, out);
}

// round 11
// speedup vs baseline: 4.0340x; 1.1444x over previous
#include <cuda_runtime.h>
#include <cuda_fp16.h>
#include <math.h>
#include <stdint.h>

// ===========================================================================
// DRConv via warp-level fp16 tensor cores (mma.sync.m16n8k16, plain sm_103):
//   out[b,o,p] = bias[o] + sum_t c[b,t,p] * (W_t (*) x)[b,o,p]
// Conv = per-tap GEMMs on zero-padded NHWC input (flat-shift im2col).
// R9: taps share one smem-resident 246-row input slab per ci-chunk
// (9x less input traffic), A tiles double-buffered via cp.async.
// Precision: x = x_hi + x_lo fp16 pair; w rounded to fp16; fp32 accum.
// ===========================================================================

#define B_    8
#define C_    128
#define O_    128
#define H_    56
#define W_    56
#define HW_   3136
#define G_    8
#define T_    8
#define PW_   58
#define PQ_   (PW_*PW_)
#define QPAD_ 3456             // 27*128
#define PROW_ 3712             // 64 guard + 3364 + guard

// ---------------- device scratch (static; zero-initialized) ----------------
__device__ __align__(128) __half g_Ph[B_*PROW_*C_];
__device__ __align__(128) __half g_Pl[B_*PROW_*C_];
__device__ __align__(128) __half g_Wh[T_*9*O_*C_];
__device__ float g_gap[B_*C_];
__device__ float g_xse[B_*64];
__device__ float g_cq[B_*T_*QPAD_];
__device__ float g_part[T_*B_*O_*QPAD_];

// ---------------- PTX helpers ----------------
__device__ __forceinline__ uint32_t smem_u32(const void* p) {
    uint32_t a;
    asm("{ .reg .u64 t; cvta.to.shared.u64 t, %1; cvt.u32.u64 %0, t; }" : "=r"(a) : "l"(p));
    return a;
}
__device__ __forceinline__ void ldm4(uint32_t r[4], uint32_t addr) {
    asm volatile("ldmatrix.sync.aligned.m8n8.x4.shared.b16 {%0,%1,%2,%3}, [%4];"
        : "=r"(r[0]), "=r"(r[1]), "=r"(r[2]), "=r"(r[3]) : "r"(addr));
}
__device__ __forceinline__ void mma16816(float d[4], const uint32_t a[4],
                                         uint32_t b0, uint32_t b1) {
    asm volatile("mma.sync.aligned.m16n8k16.row.col.f32.f16.f16.f32 "
        "{%0,%1,%2,%3}, {%4,%5,%6,%7}, {%8,%9}, {%0,%1,%2,%3};"
        : "+f"(d[0]), "+f"(d[1]), "+f"(d[2]), "+f"(d[3])
        : "r"(a[0]), "r"(a[1]), "r"(a[2]), "r"(a[3]), "r"(b0), "r"(b1));
}
__device__ __forceinline__ void cpasync16(uint32_t saddr, const void* g) {
    asm volatile("cp.async.cg.shared.global [%0], [%1], 16;" :: "r"(saddr), "l"(g));
}

// ---------------------------------------------------------------------------
// Prep: padded NHWC hi/lo fp16 split of input (transpose via smem)
// ---------------------------------------------------------------------------
__global__ void prep_p_kernel(const float* __restrict__ inputs) {
    __shared__ float tile[128 * 57];
    int h = blockIdx.x, b = blockIdx.y, tid = threadIdx.x;
    for (int idx = tid; idx < 128 * 56; idx += 256) {
        int ci = idx / 56, w = idx % 56;
        tile[ci * 57 + w] = inputs[(((size_t)b * C_ + ci) * H_ + h) * W_ + w];
    }
    __syncthreads();
    for (int idx = tid; idx < 56 * 128; idx += 256) {
        int w = idx >> 7, ci = idx & 127;
        float x = tile[ci * 57 + w];
        __half hi = __float2half(x);
        __half lo = __float2half(x - __half2float(hi));
        size_t row = (size_t)b * PROW_ + 64 + (h + 1) * PW_ + (w + 1);
        g_Ph[row * C_ + ci] = hi;
        g_Pl[row * C_ + ci] = lo;
    }
}

__global__ void prep_w_kernel(const float* __restrict__ wt) {
    int idx = blockIdx.x * 256 + threadIdx.x;
    if (idx >= T_ * 9 * O_ * C_) return;
    int ci = idx & 127;
    int o  = (idx >> 7) & 127;
    int tt = idx >> 14;
    int t = tt / 9, tap = tt % 9;
    g_Wh[idx] = __float2half(wt[((size_t)o * 1152 + ci * 9 + tap) * 8 + t]);
}

// ---------------------------------------------------------------------------
// Routing
// ---------------------------------------------------------------------------
__global__ void gap_kernel(const float* __restrict__ inputs) {
    int bc = blockIdx.x;
    const float* p = inputs + (size_t)bc * HW_;
    float s = 0.f;
    for (int i = threadIdx.x; i < HW_; i += 256) s += p[i];
    __shared__ float red[8];
    for (int off = 16; off > 0; off >>= 1) s += __shfl_down_sync(0xffffffffu, s, off);
    int lane = threadIdx.x & 31, wid = threadIdx.x >> 5;
    if (lane == 0) red[wid] = s;
    __syncthreads();
    if (wid == 0) {
        s = (lane < 8) ? red[lane] : 0.f;
        for (int off = 4; off > 0; off >>= 1) s += __shfl_down_sync(0xffffffffu, s, off);
        if (lane == 0) g_gap[bc] = s / (float)HW_;
    }
}
// grid 8, block 256: 4 threads per output j
__global__ void xse_kernel(const float* __restrict__ routing_w,
                           const float* __restrict__ routing_b) {
    int b = blockIdx.x;
    int j = threadIdx.x >> 2, sl = threadIdx.x & 3;
    __shared__ float sg[128];
    if (threadIdx.x < 128) sg[threadIdx.x] = g_gap[b * C_ + threadIdx.x];
    __syncthreads();
    float s = 0.f;
    #pragma unroll 8
    for (int c = sl; c < C_; c += 4) s += sg[c] * routing_w[j * C_ + c];
    s += __shfl_xor_sync(0xffffffffu, s, 1);
    s += __shfl_xor_sync(0xffffffffu, s, 2);
    if (sl == 0) g_xse[b * 64 + j] = 0.25f / (1.f + expf(-(s + routing_b[j])));
}

// ---------------------------------------------------------------------------
// Per-pixel coefficients on padded q grid (0 on borders)
// ---------------------------------------------------------------------------
__global__ void coeff_kernel(const float* __restrict__ Alpha,
                             const int* __restrict__ mask,
                             const void* __restrict__ use_alpha_ptr) {
    int b = blockIdx.y;
    int q = blockIdx.x * 128 + threadIdx.x;
    __shared__ float sx[64];
    if (threadIdx.x < 64) sx[threadIdx.x] = g_xse[b * 64 + threadIdx.x];
    __syncthreads();
    if (q >= QPAD_) return;
    int h = q / PW_ - 1, w = q % PW_ - 1;
    bool valid = (h >= 0 && h < H_ && w >= 0 && w < W_ && q < PQ_);
    if (!valid) {
        #pragma unroll
        for (int t = 0; t < T_; t++) g_cq[((size_t)b * T_ + t) * QPAD_ + q] = 0.f;
        return;
    }
    int p = h * W_ + w;
    bool ua = true;
    if (use_alpha_ptr) ua = (*(const int*)use_alpha_ptr) != 0;
    float pr[G_];
    if (ua) {
        float a[G_], m = -1e30f;
        #pragma unroll
        for (int g = 0; g < G_; g++) {
            a[g] = Alpha[((size_t)b * G_ + g) * HW_ + p];
            m = fmaxf(m, a[g]);
        }
        float sum = 0.f;
        #pragma unroll
        for (int g = 0; g < G_; g++) { pr[g] = expf(a[g] - m); sum += pr[g]; }
        float inv = 1.f / sum;
        #pragma unroll
        for (int g = 0; g < G_; g++) pr[g] *= inv;
    } else {
        int mk = mask[(size_t)b * HW_ + p];
        #pragma unroll
        for (int g = 0; g < G_; g++) pr[g] = (g == mk) ? 1.f : 0.f;
    }
    #pragma unroll
    for (int t = 0; t < T_; t++) {
        float s = 0.f;
        #pragma unroll
        for (int g = 0; g < G_; g++) s += pr[g] * sx[g * 8 + t];
        g_cq[((size_t)b * T_ + t) * QPAD_ + q] = s;
    }
}

// ---------------------------------------------------------------------------
// Conv. Grid (27, 8, 8) = (qg, t, b); 256 threads, 8 warps (4 m x 2 n).
// Per ci-chunk (64): one resident 246-row B slab (hi+lo), 9 taps index it
// by row offset; A tiles (128oc x 64ci) double-buffered via cp.async.
// Row stride 144B -> conflict-free ldmatrix/cp.async.
// ---------------------------------------------------------------------------
#define STR_    144
#define NROW_   246
#define BH_OFF_ 0
#define BL_OFF_ (NROW_ * STR_)            // 35424
#define A_OFF_  (2 * NROW_ * STR_)        // 70848
#define ASZ_    (128 * STR_)              // 18432
#define CS_OFF_ (A_OFF_ + 2 * ASZ_)       // 107712
#define SMEM2_  (CS_OFF_ + 512)           // 108224

__global__ __launch_bounds__(256, 2) void conv_mma_kernel() {
    extern __shared__ char sb[];
    const uint32_t s0 = smem_u32(sb);
    const int tid  = threadIdx.x;
    const int lane = tid & 31, wid = tid >> 5;
    const int wm = wid >> 1, wn = wid & 1;
    const int q0 = blockIdx.x * 128;
    const int t  = blockIdx.y;
    const int b  = blockIdx.z;

    if (tid < 128)
        ((float*)(sb + CS_OFF_))[tid] = g_cq[((size_t)b * T_ + t) * QPAD_ + q0 + tid];

    const size_t prow0 = (size_t)b * PROW_ + 64 + q0;
    const int lr = (lane & 7) + ((lane >> 3) & 1) * 8;
    const int kg = lane >> 4;

    float d[2][8][4];
    #pragma unroll
    for (int i = 0; i < 2; i++)
        #pragma unroll
        for (int j = 0; j < 8; j++)
            #pragma unroll
            for (int k = 0; k < 4; k++) d[i][j][k] = 0.f;

    auto issueA = [&](int tap, int chunk) {
        const __half* gA = g_Wh + ((size_t)t * 9 + tap) * (128 * 128) + chunk * 64;
        uint32_t dst = s0 + A_OFF_ + (tap & 1) * ASZ_;
        #pragma unroll
        for (int it = 0; it < 4; it++) {
            int idx = it * 256 + tid;
            int row = idx >> 3, q = idx & 7;
            cpasync16(dst + row * STR_ + q * 16, gA + (size_t)row * 128 + q * 8);
        }
        asm volatile("cp.async.commit_group;" ::: "memory");
    };
    auto issueB = [&](int chunk) {
        const size_t gRow0 = prow0 - 59;
        for (int idx = tid; idx < NROW_ * 8; idx += 256) {
            int row = idx >> 3, q = idx & 7;
            size_t go = (gRow0 + row) * 128 + chunk * 64 + q * 8;
            cpasync16(s0 + BH_OFF_ + row * STR_ + q * 16, g_Ph + go);
            cpasync16(s0 + BL_OFF_ + row * STR_ + q * 16, g_Pl + go);
        }
        asm volatile("cp.async.commit_group;" ::: "memory");
    };

    #pragma unroll 1
    for (int chunk = 0; chunk < 2; chunk++) {
        issueB(chunk);
        issueA(0, chunk);
        #pragma unroll 1
        for (int tap = 0; tap < 9; tap++) {
            __syncthreads();                       // prev readers of A buf done
            if (tap < 8) {
                issueA(tap + 1, chunk);
                asm volatile("cp.async.wait_group 1;" ::: "memory");
            } else {
                asm volatile("cp.async.wait_group 0;" ::: "memory");
            }
            __syncthreads();

            const uint32_t abase = s0 + A_OFF_ + (tap & 1) * ASZ_;
            const int d59 = (tap / 3) * PW_ + (tap % 3);   // row offset in slab
            #pragma unroll
            for (int ks = 0; ks < 4; ks++) {
                const uint32_t koff = ks * 32 + kg * 16;
                uint32_t a0[4], a1[4];
                ldm4(a0, abase + (wm * 32 + 0  + lr) * STR_ + koff);
                ldm4(a1, abase + (wm * 32 + 16 + lr) * STR_ + koff);
                #pragma unroll
                for (int pr = 0; pr < 4; pr++) {
                    const int rowb = wn * 64 + pr * 16 + lr + d59;
                    uint32_t bh[4], bl[4];
                    ldm4(bh, s0 + BH_OFF_ + rowb * STR_ + koff);
                    ldm4(bl, s0 + BL_OFF_ + rowb * STR_ + koff);
                    mma16816(d[0][2*pr],   a0, bh[0], bh[2]);
                    mma16816(d[0][2*pr+1], a0, bh[1], bh[3]);
                    mma16816(d[1][2*pr],   a1, bh[0], bh[2]);
                    mma16816(d[1][2*pr+1], a1, bh[1], bh[3]);
                    mma16816(d[0][2*pr],   a0, bl[0], bl[2]);
                    mma16816(d[0][2*pr+1], a0, bl[1], bl[3]);
                    mma16816(d[1][2*pr],   a1, bl[0], bl[2]);
                    mma16816(d[1][2*pr+1], a1, bl[1], bl[3]);
                }
            }
        }
        __syncthreads();   // all reads of B slab done before next chunk reload
    }

    // epilogue: scale by c[t][px], write partials
    const float* cs = (const float*)(sb + CS_OFF_);
    float* pbase = g_part + (((size_t)t * B_ + b) * O_) * QPAD_;
    const int r0 = lane >> 2;
    const int c0 = 2 * (lane & 3);
    #pragma unroll
    for (int mt = 0; mt < 2; mt++) {
        int oc = wm * 32 + mt * 16 + r0;
        #pragma unroll
        for (int nt = 0; nt < 8; nt++) {
            int px = wn * 64 + nt * 8 + c0;
            float cc0 = cs[px], cc1 = cs[px + 1];
            float2 v0 = make_float2(d[mt][nt][0] * cc0, d[mt][nt][1] * cc1);
            float2 v1 = make_float2(d[mt][nt][2] * cc0, d[mt][nt][3] * cc1);
            *(float2*)(pbase + (size_t)oc * QPAD_ + q0 + px) = v0;
            *(float2*)(pbase + (size_t)(oc + 8) * QPAD_ + q0 + px) = v1;
        }
    }
}

// ---------------------------------------------------------------------------
// Combine: out = bias + sum over 8 template partials
// ---------------------------------------------------------------------------
__global__ void combine_kernel(const float* __restrict__ bias,
                               float* __restrict__ out) {
    size_t idx = (size_t)blockIdx.x * 256 + threadIdx.x;
    int p   = (int)(idx % HW_);
    int rem = (int)(idx / HW_);
    int o   = rem & 127;
    int b   = rem >> 7;
    int h = p / W_, w = p % W_;
    int q = (h + 1) * PW_ + (w + 1);
    float s = bias[o];
    #pragma unroll
    for (int t = 0; t < T_; t++)
        s += g_part[(((size_t)t * B_ + b) * O_ + o) * QPAD_ + q];
    out[idx] = s;
}

// ---------------------------------------------------------------------------
extern "C" void kernel_launch(void* const* d_in, const int* in_sizes, int n_in,
                              void* d_out, int out_size) {
    const float* inputs     = (const float*)d_in[0];
    const int*   mask       = (const int*)  d_in[1];
    const float* Alpha      = (const float*)d_in[2];
    const float* wt         = (const float*)d_in[3];
    const float* routing_w  = (const float*)d_in[4];
    const float* routing_b  = (const float*)d_in[5];
    const float* bias       = (const float*)d_in[6];
    const void*  use_alpha  = (n_in > 7) ? d_in[7] : nullptr;
    float* out = (float*)d_out;

    cudaFuncSetAttribute(conv_mma_kernel,
                         cudaFuncAttributeMaxDynamicSharedMemorySize, SMEM2_);

    prep_w_kernel<<<(T_ * 9 * O_ * C_ + 255) / 256, 256>>>(wt);
    prep_p_kernel<<<dim3(H_, B_), 256>>>(inputs);
    gap_kernel<<<B_ * C_, 256>>>(inputs);
    xse_kernel<<<B_, 256>>>(routing_w, routing_b);
    coeff_kernel<<<dim3(QPAD_ / 128, B_), 128>>>(Alpha, mask, use_alpha);
    conv_mma_kernel<<<dim3(QPAD_ / 128, T_, B_), 256, SMEM2_>>>();
    combine_kernel<<<(B_ * O_ * HW_) / 256, 256>>>(bias, out);
}

// round 12
// speedup vs baseline: 6.2503x; 1.5494x over previous
#include <cuda_runtime.h>
#include <cuda_fp16.h>
#include <math.h>
#include <stdint.h>

// ===========================================================================
// DRConv via warp-level fp16 tensor cores (mma.sync.m16n8k16, plain sm_103):
//   out[b,o,p] = bias[o] + sum_t c[b,t,p] * (W_t (*) x)[b,o,p]
// R12: single-term fp16 (w and x rounded once; fp32 accumulate), 4 templates
// fused per CTA with in-register c_t folding; 246-row resident input slab
// per ci-chunk; A tiles double-buffered cp.async. Two template-halves write
// partials summed by a tiny combine kernel.
// ===========================================================================

#define B_    8
#define C_    128
#define O_    128
#define H_    56
#define W_    56
#define HW_   3136
#define G_    8
#define T_    8
#define PW_   58
#define PQ_   (PW_*PW_)
#define QPAD_ 3456             // 27*128
#define PROW_ 3712             // 64 guard + 3364 + guard

// ---------------- device scratch (static) ----------------
__device__ __align__(128) __half g_Ph[B_*PROW_*C_];     // 7.6 MB padded input
__device__ __align__(128) __half g_Wh[T_*9*O_*C_];      // 2.36 MB weights
__device__ float g_gap[B_*C_];
__device__ float g_xse[B_*64];
__device__ float g_cq[B_*T_*QPAD_];
__device__ float g_p2[2*B_*O_*QPAD_];                   // 28.3 MB half-partials

// ---------------- PTX helpers ----------------
__device__ __forceinline__ uint32_t smem_u32(const void* p) {
    uint32_t a;
    asm("{ .reg .u64 t; cvta.to.shared.u64 t, %1; cvt.u32.u64 %0, t; }" : "=r"(a) : "l"(p));
    return a;
}
__device__ __forceinline__ void ldm4(uint32_t r[4], uint32_t addr) {
    asm volatile("ldmatrix.sync.aligned.m8n8.x4.shared.b16 {%0,%1,%2,%3}, [%4];"
        : "=r"(r[0]), "=r"(r[1]), "=r"(r[2]), "=r"(r[3]) : "r"(addr));
}
__device__ __forceinline__ void mma16816(float d[4], const uint32_t a[4],
                                         uint32_t b0, uint32_t b1) {
    asm volatile("mma.sync.aligned.m16n8k16.row.col.f32.f16.f16.f32 "
        "{%0,%1,%2,%3}, {%4,%5,%6,%7}, {%8,%9}, {%0,%1,%2,%3};"
        : "+f"(d[0]), "+f"(d[1]), "+f"(d[2]), "+f"(d[3])
        : "r"(a[0]), "r"(a[1]), "r"(a[2]), "r"(a[3]), "r"(b0), "r"(b1));
}
__device__ __forceinline__ void cpasync16(uint32_t saddr, const void* g) {
    asm volatile("cp.async.cg.shared.global [%0], [%1], 16;" :: "r"(saddr), "l"(g));
}
#define CP_COMMIT() asm volatile("cp.async.commit_group;" ::: "memory")

// ---------------------------------------------------------------------------
// Prep: padded NHWC fp16 input (transpose via smem)
// ---------------------------------------------------------------------------
__global__ void prep_p_kernel(const float* __restrict__ inputs) {
    __shared__ float tile[128 * 57];
    int h = blockIdx.x, b = blockIdx.y, tid = threadIdx.x;
    for (int idx = tid; idx < 128 * 56; idx += 256) {
        int ci = idx / 56, w = idx % 56;
        tile[ci * 57 + w] = inputs[(((size_t)b * C_ + ci) * H_ + h) * W_ + w];
    }
    __syncthreads();
    for (int idx = tid; idx < 56 * 128; idx += 256) {
        int w = idx >> 7, ci = idx & 127;
        size_t row = (size_t)b * PROW_ + 64 + (h + 1) * PW_ + (w + 1);
        g_Ph[row * C_ + ci] = __float2half(tile[ci * 57 + w]);
    }
}

__global__ void prep_w_kernel(const float* __restrict__ wt) {
    int idx = blockIdx.x * 256 + threadIdx.x;
    if (idx >= T_ * 9 * O_ * C_) return;
    int ci = idx & 127;
    int o  = (idx >> 7) & 127;
    int tt = idx >> 14;
    int t = tt / 9, tap = tt % 9;
    g_Wh[idx] = __float2half(wt[((size_t)o * 1152 + ci * 9 + tap) * 8 + t]);
}

// ---------------------------------------------------------------------------
// Routing
// ---------------------------------------------------------------------------
__global__ void gap_kernel(const float* __restrict__ inputs) {
    int bc = blockIdx.x;
    const float* p = inputs + (size_t)bc * HW_;
    float s = 0.f;
    for (int i = threadIdx.x; i < HW_; i += 256) s += p[i];
    __shared__ float red[8];
    for (int off = 16; off > 0; off >>= 1) s += __shfl_down_sync(0xffffffffu, s, off);
    int lane = threadIdx.x & 31, wid = threadIdx.x >> 5;
    if (lane == 0) red[wid] = s;
    __syncthreads();
    if (wid == 0) {
        s = (lane < 8) ? red[lane] : 0.f;
        for (int off = 4; off > 0; off >>= 1) s += __shfl_down_sync(0xffffffffu, s, off);
        if (lane == 0) g_gap[bc] = s / (float)HW_;
    }
}
__global__ void xse_kernel(const float* __restrict__ routing_w,
                           const float* __restrict__ routing_b) {
    int b = blockIdx.x;
    int j = threadIdx.x >> 2, sl = threadIdx.x & 3;
    __shared__ float sg[128];
    if (threadIdx.x < 128) sg[threadIdx.x] = g_gap[b * C_ + threadIdx.x];
    __syncthreads();
    float s = 0.f;
    #pragma unroll 8
    for (int c = sl; c < C_; c += 4) s += sg[c] * routing_w[j * C_ + c];
    s += __shfl_xor_sync(0xffffffffu, s, 1);
    s += __shfl_xor_sync(0xffffffffu, s, 2);
    if (sl == 0) g_xse[b * 64 + j] = 0.25f / (1.f + expf(-(s + routing_b[j])));
}

// ---------------------------------------------------------------------------
// Per-pixel coefficients on padded q grid (0 on borders)
// ---------------------------------------------------------------------------
__global__ void coeff_kernel(const float* __restrict__ Alpha,
                             const int* __restrict__ mask,
                             const void* __restrict__ use_alpha_ptr) {
    int b = blockIdx.y;
    int q = blockIdx.x * 128 + threadIdx.x;
    __shared__ float sx[64];
    if (threadIdx.x < 64) sx[threadIdx.x] = g_xse[b * 64 + threadIdx.x];
    __syncthreads();
    if (q >= QPAD_) return;
    int h = q / PW_ - 1, w = q % PW_ - 1;
    bool valid = (h >= 0 && h < H_ && w >= 0 && w < W_ && q < PQ_);
    if (!valid) {
        #pragma unroll
        for (int t = 0; t < T_; t++) g_cq[((size_t)b * T_ + t) * QPAD_ + q] = 0.f;
        return;
    }
    int p = h * W_ + w;
    bool ua = true;
    if (use_alpha_ptr) ua = (*(const int*)use_alpha_ptr) != 0;
    float pr[G_];
    if (ua) {
        float a[G_], m = -1e30f;
        #pragma unroll
        for (int g = 0; g < G_; g++) {
            a[g] = Alpha[((size_t)b * G_ + g) * HW_ + p];
            m = fmaxf(m, a[g]);
        }
        float sum = 0.f;
        #pragma unroll
        for (int g = 0; g < G_; g++) { pr[g] = expf(a[g] - m); sum += pr[g]; }
        float inv = 1.f / sum;
        #pragma unroll
        for (int g = 0; g < G_; g++) pr[g] *= inv;
    } else {
        int mk = mask[(size_t)b * HW_ + p];
        #pragma unroll
        for (int g = 0; g < G_; g++) pr[g] = (g == mk) ? 1.f : 0.f;
    }
    #pragma unroll
    for (int t = 0; t < T_; t++) {
        float s = 0.f;
        #pragma unroll
        for (int g = 0; g < G_; g++) s += pr[g] * sx[g * 8 + t];
        g_cq[((size_t)b * T_ + t) * QPAD_ + q] = s;
    }
}

// ---------------------------------------------------------------------------
// Conv. Grid (27, 2, 8) = (qg, template-half, b); 256 thr, 8 warps (4m x 2n).
// Each CTA: 4 templates, folded in registers with per-pixel c_t at template
// boundaries (per ci-chunk; exact by linearity). Stages s = chunk*36+tt*9+tap,
// A tiles double-buffered; two resident B slabs (one per ci-chunk).
// ---------------------------------------------------------------------------
#define STR_    144
#define NROW_   246
#define SLABSZ_ (NROW_ * STR_)            // 35424
#define A_OFF_  (2 * SLABSZ_)             // 70848
#define ASZ_    (128 * STR_)              // 18432
#define CS_OFF_ (A_OFF_ + 2 * ASZ_)       // 107712
#define SMEM2_  (CS_OFF_ + 4 * 128 * 4)   // 109760

__global__ __launch_bounds__(256, 1) void conv_mma_kernel() {
    extern __shared__ char sb[];
    const uint32_t s0 = smem_u32(sb);
    const int tid  = threadIdx.x;
    const int lane = tid & 31, wid = tid >> 5;
    const int wm = wid >> 1, wn = wid & 1;
    const int q0   = blockIdx.x * 128;
    const int half = blockIdx.y;
    const int b    = blockIdx.z;
    const int t0   = half * 4;

    float* cs = (float*)(sb + CS_OFF_);
    #pragma unroll
    for (int i = tid; i < 512; i += 256) {
        int tt = i >> 7, px = i & 127;
        cs[i] = g_cq[((size_t)b * T_ + t0 + tt) * QPAD_ + q0 + px];
    }

    const size_t prow0 = (size_t)b * PROW_ + 64 + q0;
    const int lr = (lane & 7) + ((lane >> 3) & 1) * 8;
    const int kg = lane >> 4;

    float acc[2][8][4];
    float d[2][8][4];
    #pragma unroll
    for (int i = 0; i < 2; i++)
        #pragma unroll
        for (int j = 0; j < 8; j++)
            #pragma unroll
            for (int k = 0; k < 4; k++) { acc[i][j][k] = 0.f; d[i][j][k] = 0.f; }

    auto issueA = [&](int s) {
        int chunk = (s >= 36) ? 1 : 0;
        int rem = s - chunk * 36;
        int tt = rem / 9, tap = rem % 9;
        const __half* gA = g_Wh + ((size_t)(t0 + tt) * 9 + tap) * (128 * 128) + chunk * 64;
        uint32_t dst = s0 + A_OFF_ + (s & 1) * ASZ_;
        #pragma unroll
        for (int it = 0; it < 4; it++) {
            int idx = it * 256 + tid;
            int row = idx >> 3, q = idx & 7;
            cpasync16(dst + row * STR_ + q * 16, gA + (size_t)row * 128 + q * 8);
        }
    };
    auto issueB = [&](int c) {
        const size_t gRow0 = prow0 - 59;
        uint32_t dst = s0 + c * SLABSZ_;
        for (int idx = tid; idx < NROW_ * 8; idx += 256) {
            int row = idx >> 3, q = idx & 7;
            cpasync16(dst + row * STR_ + q * 16,
                      g_Ph + (gRow0 + row) * 128 + c * 64 + q * 8);
        }
    };

    issueB(0); issueA(0); CP_COMMIT();
    issueB(1); issueA(1); CP_COMMIT();

    #pragma unroll 1
    for (int s = 0; s < 72; s++) {
        if (s < 70) asm volatile("cp.async.wait_group 1;" ::: "memory");
        else        asm volatile("cp.async.wait_group 0;" ::: "memory");
        __syncthreads();

        const int chunk = (s >= 36) ? 1 : 0;
        const int rem = s - chunk * 36;
        const int tap = rem % 9;
        const uint32_t abase = s0 + A_OFF_ + (s & 1) * ASZ_;
        const uint32_t bbase = s0 + chunk * SLABSZ_;
        const int d59 = (tap / 3) * PW_ + (tap % 3);

        #pragma unroll
        for (int ks = 0; ks < 4; ks++) {
            const uint32_t koff = ks * 32 + kg * 16;
            uint32_t a0[4], a1[4];
            ldm4(a0, abase + (wm * 32 + 0  + lr) * STR_ + koff);
            ldm4(a1, abase + (wm * 32 + 16 + lr) * STR_ + koff);
            #pragma unroll
            for (int pr = 0; pr < 4; pr++) {
                const int rowb = wn * 64 + pr * 16 + lr + d59;
                uint32_t bh[4];
                ldm4(bh, bbase + rowb * STR_ + koff);
                mma16816(d[0][2*pr],   a0, bh[0], bh[2]);
                mma16816(d[0][2*pr+1], a0, bh[1], bh[3]);
                mma16816(d[1][2*pr],   a1, bh[0], bh[2]);
                mma16816(d[1][2*pr+1], a1, bh[1], bh[3]);
            }
        }

        if (tap == 8) {   // template boundary within this chunk: fold with c_t
            const float* cst = cs + (rem / 9) * 128;
            #pragma unroll
            for (int nt = 0; nt < 8; nt++) {
                const int px = wn * 64 + nt * 8 + 2 * (lane & 3);
                const float c0v = cst[px], c1v = cst[px + 1];
                #pragma unroll
                for (int mt = 0; mt < 2; mt++) {
                    acc[mt][nt][0] += d[mt][nt][0] * c0v;
                    acc[mt][nt][1] += d[mt][nt][1] * c1v;
                    acc[mt][nt][2] += d[mt][nt][2] * c0v;
                    acc[mt][nt][3] += d[mt][nt][3] * c1v;
                    d[mt][nt][0] = 0.f; d[mt][nt][1] = 0.f;
                    d[mt][nt][2] = 0.f; d[mt][nt][3] = 0.f;
                }
            }
        }

        __syncthreads();
        if (s + 2 < 72) { issueA(s + 2); CP_COMMIT(); }
    }

    // epilogue: write half-partials
    float* pbase = g_p2 + (((size_t)half * B_ + b) * O_) * QPAD_;
    const int r0 = lane >> 2;
    const int c0 = 2 * (lane & 3);
    #pragma unroll
    for (int mt = 0; mt < 2; mt++) {
        int oc = wm * 32 + mt * 16 + r0;
        #pragma unroll
        for (int nt = 0; nt < 8; nt++) {
            int px = wn * 64 + nt * 8 + c0;
            *(float2*)(pbase + (size_t)oc * QPAD_ + q0 + px) =
                make_float2(acc[mt][nt][0], acc[mt][nt][1]);
            *(float2*)(pbase + (size_t)(oc + 8) * QPAD_ + q0 + px) =
                make_float2(acc[mt][nt][2], acc[mt][nt][3]);
        }
    }
}

// ---------------------------------------------------------------------------
// Combine: out = bias + half0 + half1
// ---------------------------------------------------------------------------
__global__ void combine_kernel(const float* __restrict__ bias,
                               float* __restrict__ out) {
    size_t idx = (size_t)blockIdx.x * 256 + threadIdx.x;
    int p   = (int)(idx % HW_);
    int rem = (int)(idx / HW_);
    int o   = rem & 127;
    int b   = rem >> 7;
    int h = p / W_, w = p % W_;
    int q = (h + 1) * PW_ + (w + 1);
    size_t base = (((size_t)b) * O_ + o) * QPAD_ + q;
    out[idx] = bias[o] + g_p2[base] + g_p2[(size_t)B_ * O_ * QPAD_ + base];
}

// ---------------------------------------------------------------------------
extern "C" void kernel_launch(void* const* d_in, const int* in_sizes, int n_in,
                              void* d_out, int out_size) {
    const float* inputs     = (const float*)d_in[0];
    const int*   mask       = (const int*)  d_in[1];
    const float* Alpha      = (const float*)d_in[2];
    const float* wt         = (const float*)d_in[3];
    const float* routing_w  = (const float*)d_in[4];
    const float* routing_b  = (const float*)d_in[5];
    const float* bias       = (const float*)d_in[6];
    const void*  use_alpha  = (n_in > 7) ? d_in[7] : nullptr;
    float* out = (float*)d_out;

    cudaFuncSetAttribute(conv_mma_kernel,
                         cudaFuncAttributeMaxDynamicSharedMemorySize, SMEM2_);

    prep_w_kernel<<<(T_ * 9 * O_ * C_ + 255) / 256, 256>>>(wt);
    prep_p_kernel<<<dim3(H_, B_), 256>>>(inputs);
    gap_kernel<<<B_ * C_, 256>>>(inputs);
    xse_kernel<<<B_, 256>>>(routing_w, routing_b);
    coeff_kernel<<<dim3(QPAD_ / 128, B_), 128>>>(Alpha, mask, use_alpha);
    conv_mma_kernel<<<dim3(QPAD_ / 128, 2, B_), 256, SMEM2_>>>();
    combine_kernel<<<(B_ * O_ * HW_) / 256, 256>>>(bias, out);
}

// round 13
// speedup vs baseline: 6.6722x; 1.0675x over previous
#include <cuda_runtime.h>
#include <cuda_fp16.h>
#include <math.h>
#include <stdint.h>

// ===========================================================================
// DRConv via warp-level fp16 tensor cores (mma.sync.m16n8k16, plain sm_103):
//   out[b,o,p] = bias[o] + sum_t c[b,t,p] * (W_t (*) x)[b,o,p]
// R13: 36 full-K stages (1 sync/stage), 3-deep A-tile cp.async pipeline,
// both 64-ci input slabs smem-resident; 4 templates fused per CTA with
// in-register c_t folding. Single-term fp16, fp32 accumulate.
// ===========================================================================

#define B_    8
#define C_    128
#define O_    128
#define H_    56
#define W_    56
#define HW_   3136
#define G_    8
#define T_    8
#define PW_   58
#define PQ_   (PW_*PW_)
#define QPAD_ 3456             // 27*128
#define PROW_ 3712             // 64 guard + 3364 + guard

// ---------------- device scratch (static) ----------------
__device__ __align__(128) __half g_Ph[B_*PROW_*C_];     // padded fp16 input
__device__ __align__(128) __half g_Wh[T_*9*O_*C_];      // fp16 weights
__device__ float g_gap[B_*C_];
__device__ float g_xse[B_*64];
__device__ float g_cq[B_*T_*QPAD_];
__device__ float g_p2[2*B_*O_*QPAD_];                   // half-partials

// ---------------- PTX helpers ----------------
__device__ __forceinline__ uint32_t smem_u32(const void* p) {
    uint32_t a;
    asm("{ .reg .u64 t; cvta.to.shared.u64 t, %1; cvt.u32.u64 %0, t; }" : "=r"(a) : "l"(p));
    return a;
}
__device__ __forceinline__ void ldm4(uint32_t r[4], uint32_t addr) {
    asm volatile("ldmatrix.sync.aligned.m8n8.x4.shared.b16 {%0,%1,%2,%3}, [%4];"
        : "=r"(r[0]), "=r"(r[1]), "=r"(r[2]), "=r"(r[3]) : "r"(addr));
}
__device__ __forceinline__ void mma16816(float d[4], const uint32_t a[4],
                                         uint32_t b0, uint32_t b1) {
    asm volatile("mma.sync.aligned.m16n8k16.row.col.f32.f16.f16.f32 "
        "{%0,%1,%2,%3}, {%4,%5,%6,%7}, {%8,%9}, {%0,%1,%2,%3};"
        : "+f"(d[0]), "+f"(d[1]), "+f"(d[2]), "+f"(d[3])
        : "r"(a[0]), "r"(a[1]), "r"(a[2]), "r"(a[3]), "r"(b0), "r"(b1));
}
__device__ __forceinline__ void cpasync16(uint32_t saddr, const void* g) {
    asm volatile("cp.async.cg.shared.global [%0], [%1], 16;" :: "r"(saddr), "l"(g));
}
#define CP_COMMIT() asm volatile("cp.async.commit_group;" ::: "memory")

// ---------------------------------------------------------------------------
// Prep: padded NHWC fp16 input (transpose via smem)
// ---------------------------------------------------------------------------
__global__ void prep_p_kernel(const float* __restrict__ inputs) {
    __shared__ float tile[128 * 57];
    int h = blockIdx.x, b = blockIdx.y, tid = threadIdx.x;
    for (int idx = tid; idx < 128 * 56; idx += 256) {
        int ci = idx / 56, w = idx % 56;
        tile[ci * 57 + w] = inputs[(((size_t)b * C_ + ci) * H_ + h) * W_ + w];
    }
    __syncthreads();
    for (int idx = tid; idx < 56 * 128; idx += 256) {
        int w = idx >> 7, ci = idx & 127;
        size_t row = (size_t)b * PROW_ + 64 + (h + 1) * PW_ + (w + 1);
        g_Ph[row * C_ + ci] = __float2half(tile[ci * 57 + w]);
    }
}

__global__ void prep_w_kernel(const float* __restrict__ wt) {
    int idx = blockIdx.x * 256 + threadIdx.x;
    if (idx >= T_ * 9 * O_ * C_) return;
    int ci = idx & 127;
    int o  = (idx >> 7) & 127;
    int tt = idx >> 14;
    int t = tt / 9, tap = tt % 9;
    g_Wh[idx] = __float2half(wt[((size_t)o * 1152 + ci * 9 + tap) * 8 + t]);
}

// ---------------------------------------------------------------------------
// Routing
// ---------------------------------------------------------------------------
__global__ void gap_kernel(const float* __restrict__ inputs) {
    int bc = blockIdx.x;
    const float* p = inputs + (size_t)bc * HW_;
    float s = 0.f;
    for (int i = threadIdx.x; i < HW_; i += 256) s += p[i];
    __shared__ float red[8];
    for (int off = 16; off > 0; off >>= 1) s += __shfl_down_sync(0xffffffffu, s, off);
    int lane = threadIdx.x & 31, wid = threadIdx.x >> 5;
    if (lane == 0) red[wid] = s;
    __syncthreads();
    if (wid == 0) {
        s = (lane < 8) ? red[lane] : 0.f;
        for (int off = 4; off > 0; off >>= 1) s += __shfl_down_sync(0xffffffffu, s, off);
        if (lane == 0) g_gap[bc] = s / (float)HW_;
    }
}
__global__ void xse_kernel(const float* __restrict__ routing_w,
                           const float* __restrict__ routing_b) {
    int b = blockIdx.x;
    int j = threadIdx.x >> 2, sl = threadIdx.x & 3;
    __shared__ float sg[128];
    if (threadIdx.x < 128) sg[threadIdx.x] = g_gap[b * C_ + threadIdx.x];
    __syncthreads();
    float s = 0.f;
    #pragma unroll 8
    for (int c = sl; c < C_; c += 4) s += sg[c] * routing_w[j * C_ + c];
    s += __shfl_xor_sync(0xffffffffu, s, 1);
    s += __shfl_xor_sync(0xffffffffu, s, 2);
    if (sl == 0) g_xse[b * 64 + j] = 0.25f / (1.f + expf(-(s + routing_b[j])));
}

// ---------------------------------------------------------------------------
// Per-pixel coefficients on padded q grid (0 on borders)
// ---------------------------------------------------------------------------
__global__ void coeff_kernel(const float* __restrict__ Alpha,
                             const int* __restrict__ mask,
                             const void* __restrict__ use_alpha_ptr) {
    int b = blockIdx.y;
    int q = blockIdx.x * 128 + threadIdx.x;
    __shared__ float sx[64];
    if (threadIdx.x < 64) sx[threadIdx.x] = g_xse[b * 64 + threadIdx.x];
    __syncthreads();
    if (q >= QPAD_) return;
    int h = q / PW_ - 1, w = q % PW_ - 1;
    bool valid = (h >= 0 && h < H_ && w >= 0 && w < W_ && q < PQ_);
    if (!valid) {
        #pragma unroll
        for (int t = 0; t < T_; t++) g_cq[((size_t)b * T_ + t) * QPAD_ + q] = 0.f;
        return;
    }
    int p = h * W_ + w;
    bool ua = true;
    if (use_alpha_ptr) ua = (*(const int*)use_alpha_ptr) != 0;
    float pr[G_];
    if (ua) {
        float a[G_], m = -1e30f;
        #pragma unroll
        for (int g = 0; g < G_; g++) {
            a[g] = Alpha[((size_t)b * G_ + g) * HW_ + p];
            m = fmaxf(m, a[g]);
        }
        float sum = 0.f;
        #pragma unroll
        for (int g = 0; g < G_; g++) { pr[g] = expf(a[g] - m); sum += pr[g]; }
        float inv = 1.f / sum;
        #pragma unroll
        for (int g = 0; g < G_; g++) pr[g] *= inv;
    } else {
        int mk = mask[(size_t)b * HW_ + p];
        #pragma unroll
        for (int g = 0; g < G_; g++) pr[g] = (g == mk) ? 1.f : 0.f;
    }
    #pragma unroll
    for (int t = 0; t < T_; t++) {
        float s = 0.f;
        #pragma unroll
        for (int g = 0; g < G_; g++) s += pr[g] * sx[g * 8 + t];
        g_cq[((size_t)b * T_ + t) * QPAD_ + q] = s;
    }
}

// ---------------------------------------------------------------------------
// Conv. Grid (27, 2, 8) = (qg, template-half, b); 256 thr, 8 warps (4m x 2n).
// 36 stages s = tt*9 + tap, full K=128/stage. A tiles [128oc x 128ci]
// (stride 272) in a 3-buffer cp.async rotation; both 64-ci B slabs resident.
// One __syncthreads per stage. Fold acc += c_t*d at tap==8.
// ---------------------------------------------------------------------------
#define BSTR_   144
#define NROW_   246
#define SLABSZ_ (NROW_ * BSTR_)           // 35424
#define ASTR_   272
#define ASZ_    (128 * ASTR_)             // 34816
#define A_OFF_  (2 * SLABSZ_)             // 70848
#define CS_OFF_ (A_OFF_ + 3 * ASZ_)       // 175296
#define SMEM2_  (CS_OFF_ + 4 * 128 * 4)   // 177344

__global__ __launch_bounds__(256, 1) void conv_mma_kernel() {
    extern __shared__ char sb[];
    const uint32_t s0 = smem_u32(sb);
    const int tid  = threadIdx.x;
    const int lane = tid & 31, wid = tid >> 5;
    const int wm = wid >> 1, wn = wid & 1;
    const int q0   = blockIdx.x * 128;
    const int half = blockIdx.y;
    const int b    = blockIdx.z;
    const int t0   = half * 4;

    float* cs = (float*)(sb + CS_OFF_);
    #pragma unroll
    for (int i = tid; i < 512; i += 256) {
        int tt = i >> 7, px = i & 127;
        cs[i] = g_cq[((size_t)b * T_ + t0 + tt) * QPAD_ + q0 + px];
    }

    const size_t prow0 = (size_t)b * PROW_ + 64 + q0;
    const int lr = (lane & 7) + ((lane >> 3) & 1) * 8;
    const int kg = lane >> 4;

    float acc[2][8][4];
    float d[2][8][4];
    #pragma unroll
    for (int i = 0; i < 2; i++)
        #pragma unroll
        for (int j = 0; j < 8; j++)
            #pragma unroll
            for (int k = 0; k < 4; k++) { acc[i][j][k] = 0.f; d[i][j][k] = 0.f; }

    // A tile: full K=128 for (template tt = s/9, tap = s%9)
    auto issueA = [&](int s) {
        int tt = s / 9, tap = s - tt * 9;
        const __half* gA = g_Wh + ((size_t)(t0 + tt) * 9 + tap) * (128 * 128);
        uint32_t dst = s0 + A_OFF_ + (s % 3) * ASZ_;
        #pragma unroll
        for (int it = 0; it < 8; it++) {
            int idx = it * 256 + tid;
            int row = idx >> 4, q = idx & 15;
            cpasync16(dst + row * ASTR_ + q * 16, gA + (size_t)row * 128 + q * 8);
        }
    };
    auto issueB = [&](int c) {
        const size_t gRow0 = prow0 - 59;
        uint32_t dst = s0 + c * SLABSZ_;
        for (int idx = tid; idx < NROW_ * 8; idx += 256) {
            int row = idx >> 3, q = idx & 7;
            cpasync16(dst + row * BSTR_ + q * 16,
                      g_Ph + (gRow0 + row) * 128 + c * 64 + q * 8);
        }
    };

    issueB(0); issueB(1); issueA(0); CP_COMMIT();   // group 0
    issueA(1); CP_COMMIT();                          // group 1

    #pragma unroll 1
    for (int s = 0; s < 36; s++) {
        if (s < 34) asm volatile("cp.async.wait_group 1;" ::: "memory");
        else        asm volatile("cp.async.wait_group 0;" ::: "memory");
        __syncthreads();
        if (s + 2 < 36) { issueA(s + 2); CP_COMMIT(); }

        const int tap = s % 9;
        const uint32_t abase = s0 + A_OFF_ + (s % 3) * ASZ_;
        const int d59 = (tap / 3) * PW_ + (tap % 3);

        #pragma unroll
        for (int ks = 0; ks < 8; ks++) {
            const uint32_t akoff = ks * 32 + kg * 16;
            const uint32_t bbase = s0 + (ks >> 2) * SLABSZ_;
            const uint32_t bkoff = (ks & 3) * 32 + kg * 16;
            uint32_t a0[4], a1[4];
            ldm4(a0, abase + (wm * 32 + 0  + lr) * ASTR_ + akoff);
            ldm4(a1, abase + (wm * 32 + 16 + lr) * ASTR_ + akoff);
            #pragma unroll
            for (int pr = 0; pr < 4; pr++) {
                const int rowb = wn * 64 + pr * 16 + lr + d59;
                uint32_t bh[4];
                ldm4(bh, bbase + rowb * BSTR_ + bkoff);
                mma16816(d[0][2*pr],   a0, bh[0], bh[2]);
                mma16816(d[0][2*pr+1], a0, bh[1], bh[3]);
                mma16816(d[1][2*pr],   a1, bh[0], bh[2]);
                mma16816(d[1][2*pr+1], a1, bh[1], bh[3]);
            }
        }

        if (tap == 8) {   // template finished: fold with c_t
            const float* cst = cs + (s / 9) * 128;
            #pragma unroll
            for (int nt = 0; nt < 8; nt++) {
                const int px = wn * 64 + nt * 8 + 2 * (lane & 3);
                const float c0v = cst[px], c1v = cst[px + 1];
                #pragma unroll
                for (int mt = 0; mt < 2; mt++) {
                    acc[mt][nt][0] += d[mt][nt][0] * c0v;
                    acc[mt][nt][1] += d[mt][nt][1] * c1v;
                    acc[mt][nt][2] += d[mt][nt][2] * c0v;
                    acc[mt][nt][3] += d[mt][nt][3] * c1v;
                    d[mt][nt][0] = 0.f; d[mt][nt][1] = 0.f;
                    d[mt][nt][2] = 0.f; d[mt][nt][3] = 0.f;
                }
            }
        }
    }

    // epilogue: write half-partials
    float* pbase = g_p2 + (((size_t)half * B_ + b) * O_) * QPAD_;
    const int r0 = lane >> 2;
    const int c0 = 2 * (lane & 3);
    #pragma unroll
    for (int mt = 0; mt < 2; mt++) {
        int oc = wm * 32 + mt * 16 + r0;
        #pragma unroll
        for (int nt = 0; nt < 8; nt++) {
            int px = wn * 64 + nt * 8 + c0;
            *(float2*)(pbase + (size_t)oc * QPAD_ + q0 + px) =
                make_float2(acc[mt][nt][0], acc[mt][nt][1]);
            *(float2*)(pbase + (size_t)(oc + 8) * QPAD_ + q0 + px) =
                make_float2(acc[mt][nt][2], acc[mt][nt][3]);
        }
    }
}

// ---------------------------------------------------------------------------
// Combine: out = bias + half0 + half1
// ---------------------------------------------------------------------------
__global__ void combine_kernel(const float* __restrict__ bias,
                               float* __restrict__ out) {
    size_t idx = (size_t)blockIdx.x * 256 + threadIdx.x;
    int p   = (int)(idx % HW_);
    int rem = (int)(idx / HW_);
    int o   = rem & 127;
    int b   = rem >> 7;
    int h = p / W_, w = p % W_;
    int q = (h + 1) * PW_ + (w + 1);
    size_t base = (((size_t)b) * O_ + o) * QPAD_ + q;
    out[idx] = bias[o] + g_p2[base] + g_p2[(size_t)B_ * O_ * QPAD_ + base];
}

// ---------------------------------------------------------------------------
extern "C" void kernel_launch(void* const* d_in, const int* in_sizes, int n_in,
                              void* d_out, int out_size) {
    const float* inputs     = (const float*)d_in[0];
    const int*   mask       = (const int*)  d_in[1];
    const float* Alpha      = (const float*)d_in[2];
    const float* wt         = (const float*)d_in[3];
    const float* routing_w  = (const float*)d_in[4];
    const float* routing_b  = (const float*)d_in[5];
    const float* bias       = (const float*)d_in[6];
    const void*  use_alpha  = (n_in > 7) ? d_in[7] : nullptr;
    float* out = (float*)d_out;

    cudaFuncSetAttribute(conv_mma_kernel,
                         cudaFuncAttributeMaxDynamicSharedMemorySize, SMEM2_);

    prep_w_kernel<<<(T_ * 9 * O_ * C_ + 255) / 256, 256>>>(wt);
    prep_p_kernel<<<dim3(H_, B_), 256>>>(inputs);
    gap_kernel<<<B_ * C_, 256>>>(inputs);
    xse_kernel<<<B_, 256>>>(routing_w, routing_b);
    coeff_kernel<<<dim3(QPAD_ / 128, B_), 128>>>(Alpha, mask, use_alpha);
    conv_mma_kernel<<<dim3(QPAD_ / 128, 2, B_), 256, SMEM2_>>>();
    combine_kernel<<<(B_ * O_ * HW_) / 256, 256>>>(bias, out);
}